// round 2
// baseline (speedup 1.0000x reference)
#include <cuda_runtime.h>
#include <cmath>
#include <cstdint>

#define NLINK 2000
#define NFLOW 30000
#define NPATH 50000
#define E1N   120000
#define E2N   120000
#define HIDN  256
#define NH    4
#define HD    256

// ---------------- scratch (device globals; no allocation anywhere) ----------------
__device__ float g_h_link[NLINK * HIDN];
__device__ float g_h_flow[NFLOW * HIDN];
__device__ float g_h_path0[NPATH * HIDN];
__device__ float g_h_path1[NPATH * HIDN];
__device__ float g_h_path2[NPATH * HIDN];
__device__ float g_zs1[NLINK * NH * HD];
__device__ float g_zs2[NFLOW * NH * HD];
__device__ float g_el1[NLINK * NH];
__device__ float g_er1[NPATH * NH];
__device__ float g_el2[NFLOW * NH];
__device__ float g_er2[NPATH * NH];
__device__ float g_elog[E1N * NH];
__device__ float g_m[NPATH * NH];
__device__ float g_denom[NPATH * NH];
__device__ float g_agg[NPATH * HIDN];
__device__ float g_xcat[NPATH * 2 * HIDN];
__device__ float g_hidden[NPATH * HIDN];
__device__ float g_wl1[HIDN * NH];
__device__ float g_wr1[HIDN * NH];
__device__ float g_wl2[HIDN * NH];
__device__ float g_wr2[HIDN * NH];
__device__ float g_ce[NH];
__device__ float g_wcat[2 * HIDN * HIDN];

// ---------------- helpers ----------------
__device__ __forceinline__ void atomicMaxFloat(float* addr, float v) {
    // sign-split trick: exact float max via integer atomics
    if (v >= 0.0f) atomicMax((int*)addr, __float_as_int(v));
    else           atomicMin((unsigned int*)addr, __float_as_uint(v));
}

__global__ void fill_kernel(float* __restrict__ p, float v, int n) {
    int i = blockIdx.x * blockDim.x + threadIdx.x;
    if (i < n) p[i] = v;
}

// out[row*256+c] = relu(bias[c] + sum_k x[row*Kin+k]*W[k*256+c])
__global__ void proj_relu(const float* __restrict__ x, const float* __restrict__ W,
                          const float* __restrict__ b, float* __restrict__ out,
                          int M, int Kin) {
    int idx = blockIdx.x * blockDim.x + threadIdx.x;
    if (idx >= M * HIDN) return;
    int row = idx >> 8, c = idx & 255;
    float s = b[c];
    const float* xr = x + (size_t)row * Kin;
    for (int k = 0; k < Kin; ++k) s += xr[k] * W[k * HIDN + c];
    out[idx] = fmaxf(s, 0.0f);
}

// out[k*4+h] = sum_d fc[k*1024 + h*256 + d] * attn[h*256+d]
__global__ void attn_reduce(const float* __restrict__ fc, const float* __restrict__ attn,
                            float* __restrict__ out) {
    int idx = blockIdx.x * blockDim.x + threadIdx.x;
    if (idx >= HIDN * NH) return;
    int k = idx >> 2, h = idx & 3;
    float s = 0.0f;
    const float* f = fc + (size_t)k * (NH * HD) + h * HD;
    const float* a = attn + h * HD;
    for (int d = 0; d < HD; ++d) s += f[d] * a[d];
    out[idx] = s;
}

// ce[h] = sum_d fc_e1[h*256+d]*attn_e1[h*256+d]
__global__ void ce_kernel(const float* __restrict__ fc_e1, const float* __restrict__ attn_e1,
                          float* __restrict__ ce) {
    int h = threadIdx.x;
    if (h >= NH) return;
    float s = 0.0f;
    for (int d = 0; d < HD; ++d) s += fc_e1[h * HD + d] * attn_e1[h * HD + d];
    ce[h] = s;
}

// out[i*4+h] = sum_k hfeat[i*256+k] * w[k*4+h]
__global__ void attn_score(const float* __restrict__ hfeat, const float* __restrict__ w,
                           float* __restrict__ out, int M) {
    int idx = blockIdx.x * blockDim.x + threadIdx.x;
    if (idx >= M * NH) return;
    int i = idx >> 2, h = idx & 3;
    const float* row = hfeat + (size_t)i * HIDN;
    float s = 0.0f;
    for (int k = 0; k < HIDN; ++k) s += row[k] * w[k * NH + h];
    out[idx] = s;
}

template <bool HAS_EE>
__global__ void edge_logits(const float* __restrict__ el, const float* __restrict__ er,
                            const float* __restrict__ ef, const float* __restrict__ ce,
                            const int* __restrict__ src, const int* __restrict__ dst,
                            float* __restrict__ elog, float* __restrict__ m, int E) {
    int idx = blockIdx.x * blockDim.x + threadIdx.x;
    if (idx >= E * NH) return;
    int e = idx >> 2, h = idx & 3;
    float v = el[src[e] * NH + h] + er[dst[e] * NH + h];
    if (HAS_EE) v += ef[e] * ce[h];
    v = v > 0.0f ? v : 0.2f * v;  // leaky_relu(0.2)
    elog[idx] = v;
    atomicMaxFloat(&m[dst[e] * NH + h], v);
}

__global__ void edge_exp(const float* __restrict__ mArr, const int* __restrict__ dst,
                         float* __restrict__ elog, float* __restrict__ denom, int E) {
    int idx = blockIdx.x * blockDim.x + threadIdx.x;
    if (idx >= E * NH) return;
    int e = idx >> 2, h = idx & 3;
    float a = expf(elog[idx] - mArr[dst[e] * NH + h]);
    elog[idx] = a;
    atomicAdd(&denom[dst[e] * NH + h], a);
}

// one block (64 threads) per edge; each thread handles 4 contiguous cols (float4)
// accumulates (1/H)*sum_h alpha_h * z_src[src,h,:] into agg[dst,:]
__global__ void edge_scatter(const float* __restrict__ zs, const float* __restrict__ alog,
                             const float* __restrict__ denom,
                             const int* __restrict__ src, const int* __restrict__ dst,
                             float* __restrict__ agg, int E) {
    int e = blockIdx.x;
    if (e >= E) return;
    int t = threadIdx.x;  // 0..63
    int s = src[e], d = dst[e];
    float al[NH];
#pragma unroll
    for (int h = 0; h < NH; ++h)
        al[h] = 0.25f * alog[e * NH + h] / fmaxf(denom[d * NH + h], 1e-9f);
    const float4* z = (const float4*)(zs + (size_t)s * (NH * HD));
    float4 r = make_float4(0.f, 0.f, 0.f, 0.f);
#pragma unroll
    for (int h = 0; h < NH; ++h) {
        float4 zv = z[h * 64 + t];
        r.x += al[h] * zv.x; r.y += al[h] * zv.y;
        r.z += al[h] * zv.z; r.w += al[h] * zv.w;
    }
    float* out = agg + (size_t)d * HIDN + t * 4;
    asm volatile("red.global.add.v4.f32 [%0], {%1,%2,%3,%4};"
                 :: "l"(out), "f"(r.x), "f"(r.y), "f"(r.z), "f"(r.w) : "memory");
}

__global__ void build_xcat(const float* __restrict__ h2, const float* __restrict__ h1,
                           float* __restrict__ xcat) {
    int idx = blockIdx.x * blockDim.x + threadIdx.x;
    if (idx >= NPATH * 2 * HIDN) return;
    int row = idx >> 9, c = idx & 511;
    xcat[idx] = (c < HIDN) ? h2[(row << 8) + c] : h1[(row << 8) + c - HIDN];
}

__global__ void build_wcat(const float* __restrict__ W1, float* __restrict__ wcat) {
    int idx = blockIdx.x * blockDim.x + threadIdx.x;
    if (idx >= 2 * HIDN * HIDN) return;
    int r = idx >> 8;
    wcat[idx] = (r < HIDN) ? (W1[idx] + W1[idx + 512 * HIDN]) : W1[idx];
}

// out[row, 0..1] = hidden[row,:] @ W2 + b2   (warp per row)
__global__ void decoder_out(const float* __restrict__ hidden, const float* __restrict__ W2,
                            const float* __restrict__ b2, float* __restrict__ out) {
    int gw = (blockIdx.x * blockDim.x + threadIdx.x) >> 5;
    int lane = threadIdx.x & 31;
    if (gw >= NPATH) return;
    const float* hrow = hidden + (size_t)gw * HIDN;
    float s0 = 0.f, s1 = 0.f;
    for (int k = lane; k < HIDN; k += 32) {
        float hv = hrow[k];
        s0 += hv * W2[k * 2 + 0];
        s1 += hv * W2[k * 2 + 1];
    }
#pragma unroll
    for (int o = 16; o > 0; o >>= 1) {
        s0 += __shfl_down_sync(0xffffffffu, s0, o);
        s1 += __shfl_down_sync(0xffffffffu, s1, o);
    }
    if (lane == 0) {
        out[gw * 2 + 0] = s0 + b2[0];
        out[gw * 2 + 1] = s1 + b2[1];
    }
}

// ---------------- tiled SGEMM: C[M,N] = epi(A[M,K] @ B[K,N]) ----------------
// EPI: 0 = none, 2 = relu(+add[M,N]), 3 = relu(+bias[N])
// Requires N % 128 == 0, K % 16 == 0 (all call sites satisfy this).
template <int EPI>
__global__ __launch_bounds__(256)
void sgemm(const float* __restrict__ A, const float* __restrict__ B,
           float* __restrict__ C, int M, int N, int K,
           const float* __restrict__ add, const float* __restrict__ bias) {
    const int BM = 128, BN = 128, BK = 16;
    __shared__ float As[BK][BM];
    __shared__ float Bs[BK][BN];
    int tid = threadIdx.x;
    int row0 = blockIdx.y * BM;
    int col0 = blockIdx.x * BN;
    int tx = tid & 15, ty = tid >> 4;

    float acc[8][8];
#pragma unroll
    for (int i = 0; i < 8; ++i)
#pragma unroll
        for (int j = 0; j < 8; ++j) acc[i][j] = 0.0f;

    int aRow = tid >> 2;          // 0..63 (two passes of 64 rows)
    int aK   = (tid & 3) << 2;    // 0,4,8,12
    int bK   = tid >> 5;          // 0..7 (two passes of 8 rows)
    int bCol = (tid & 31) << 2;   // 0..124

    for (int k0 = 0; k0 < K; k0 += BK) {
#pragma unroll
        for (int p = 0; p < 2; ++p) {
            int r = row0 + aRow + p * 64;
            float4 v = make_float4(0.f, 0.f, 0.f, 0.f);
            if (r < M) v = *(const float4*)(A + (size_t)r * K + k0 + aK);
            As[aK + 0][aRow + p * 64] = v.x;
            As[aK + 1][aRow + p * 64] = v.y;
            As[aK + 2][aRow + p * 64] = v.z;
            As[aK + 3][aRow + p * 64] = v.w;
        }
#pragma unroll
        for (int p = 0; p < 2; ++p) {
            int kk = bK + p * 8;
            *(float4*)&Bs[kk][bCol] =
                *(const float4*)(B + (size_t)(k0 + kk) * N + col0 + bCol);
        }
        __syncthreads();
#pragma unroll
        for (int kk = 0; kk < BK; ++kk) {
            float ra[8], rb[8];
            *(float4*)&ra[0] = *(const float4*)&As[kk][ty * 8];
            *(float4*)&ra[4] = *(const float4*)&As[kk][ty * 8 + 4];
            *(float4*)&rb[0] = *(const float4*)&Bs[kk][tx * 8];
            *(float4*)&rb[4] = *(const float4*)&Bs[kk][tx * 8 + 4];
#pragma unroll
            for (int i = 0; i < 8; ++i)
#pragma unroll
                for (int j = 0; j < 8; ++j)
                    acc[i][j] += ra[i] * rb[j];
        }
        __syncthreads();
    }

#pragma unroll
    for (int i = 0; i < 8; ++i) {
        int r = row0 + ty * 8 + i;
        if (r >= M) continue;
#pragma unroll
        for (int j = 0; j < 8; ++j) {
            int c = col0 + tx * 8 + j;
            float v = acc[i][j];
            if (EPI == 2)      v = fmaxf(v + add[(size_t)r * N + c], 0.0f);
            else if (EPI == 3) v = fmaxf(v + bias[c], 0.0f);
            C[(size_t)r * N + c] = v;
        }
    }
}

// ---------------- host launch ----------------
static inline int cdiv(int a, int b) { return (a + b - 1) / b; }

extern "C" void kernel_launch(void* const* d_in, const int* in_sizes, int n_in,
                              void* d_out, int out_size) {
    (void)in_sizes; (void)n_in; (void)out_size;
    const float* x_link  = (const float*)d_in[0];
    const float* x_flow  = (const float*)d_in[1];
    const float* x_path  = (const float*)d_in[2];
    const float* e2p     = (const float*)d_in[3];
    const float* Wp_link = (const float*)d_in[4];
    const float* bp_link = (const float*)d_in[5];
    const float* Wp_flow = (const float*)d_in[6];
    const float* bp_flow = (const float*)d_in[7];
    const float* Wp_path = (const float*)d_in[8];
    const float* bp_path = (const float*)d_in[9];
    const float* fc_src1 = (const float*)d_in[10];
    const float* fc_dst1 = (const float*)d_in[11];
    const float* fc_e1   = (const float*)d_in[12];
    const float* attn_l1 = (const float*)d_in[13];
    const float* attn_r1 = (const float*)d_in[14];
    const float* attn_e1 = (const float*)d_in[15];
    const float* res_W1  = (const float*)d_in[16];
    const float* fc_src2 = (const float*)d_in[17];
    const float* fc_dst2 = (const float*)d_in[18];
    const float* attn_l2 = (const float*)d_in[19];
    const float* attn_r2 = (const float*)d_in[20];
    const float* res_W2  = (const float*)d_in[21];
    const float* W1      = (const float*)d_in[22];
    const float* b1      = (const float*)d_in[23];
    const float* W2      = (const float*)d_in[24];
    const float* b2      = (const float*)d_in[25];
    const int*   src1    = (const int*)d_in[26];
    const int*   dst1    = (const int*)d_in[27];
    const int*   src2    = (const int*)d_in[28];
    const int*   dst2    = (const int*)d_in[29];
    float* out = (float*)d_out;

#define SYM(p, s) float* p; cudaGetSymbolAddress((void**)&p, s)
    SYM(p_hlink, g_h_link);  SYM(p_hflow, g_h_flow);
    SYM(p_hp0, g_h_path0);   SYM(p_hp1, g_h_path1);   SYM(p_hp2, g_h_path2);
    SYM(p_zs1, g_zs1);       SYM(p_zs2, g_zs2);
    SYM(p_el1, g_el1);       SYM(p_er1, g_er1);
    SYM(p_el2, g_el2);       SYM(p_er2, g_er2);
    SYM(p_elog, g_elog);     SYM(p_m, g_m);           SYM(p_denom, g_denom);
    SYM(p_agg, g_agg);       SYM(p_xcat, g_xcat);     SYM(p_hidden, g_hidden);
    SYM(p_wl1, g_wl1);       SYM(p_wr1, g_wr1);
    SYM(p_wl2, g_wl2);       SYM(p_wr2, g_wr2);
    SYM(p_ce, g_ce);         SYM(p_wcat, g_wcat);
#undef SYM

    const int T = 256;

    // --- prep folded weights ---
    attn_reduce<<<cdiv(HIDN * NH, T), T>>>(fc_src1, attn_l1, p_wl1);
    attn_reduce<<<cdiv(HIDN * NH, T), T>>>(fc_dst1, attn_r1, p_wr1);
    attn_reduce<<<cdiv(HIDN * NH, T), T>>>(fc_src2, attn_l2, p_wl2);
    attn_reduce<<<cdiv(HIDN * NH, T), T>>>(fc_dst2, attn_r2, p_wr2);
    ce_kernel<<<1, 32>>>(fc_e1, attn_e1, p_ce);
    build_wcat<<<cdiv(2 * HIDN * HIDN, T), T>>>(W1, p_wcat);

    // --- node projections ---
    proj_relu<<<cdiv(NLINK * HIDN, T), T>>>(x_link, Wp_link, bp_link, p_hlink, NLINK, 8);
    proj_relu<<<cdiv(NFLOW * HIDN, T), T>>>(x_flow, Wp_flow, bp_flow, p_hflow, NFLOW, 16);
    proj_relu<<<cdiv(NPATH * HIDN, T), T>>>(x_path, Wp_path, bp_path, p_hp0, NPATH, 8);

    // --- z_src GEMMs ---
    {
        dim3 g1(1024 / 128, cdiv(NLINK, 128));
        sgemm<0><<<g1, T>>>(p_hlink, fc_src1, p_zs1, NLINK, 1024, 256, nullptr, nullptr);
        dim3 g2(1024 / 128, cdiv(NFLOW, 128));
        sgemm<0><<<g2, T>>>(p_hflow, fc_src2, p_zs2, NFLOW, 1024, 256, nullptr, nullptr);
    }

    // --- attn scores (z_dst never materialized) ---
    attn_score<<<cdiv(NLINK * NH, T), T>>>(p_hlink, p_wl1, p_el1, NLINK);
    attn_score<<<cdiv(NPATH * NH, T), T>>>(p_hp0, p_wr1, p_er1, NPATH);
    attn_score<<<cdiv(NFLOW * NH, T), T>>>(p_hflow, p_wl2, p_el2, NFLOW);

    // ================= conv 1: link -> path =================
    fill_kernel<<<cdiv(NPATH * NH, T), T>>>(p_m, -INFINITY, NPATH * NH);
    fill_kernel<<<cdiv(NPATH * NH, T), T>>>(p_denom, 0.0f, NPATH * NH);
    fill_kernel<<<cdiv(NPATH * HIDN, T), T>>>(p_agg, 0.0f, NPATH * HIDN);
    edge_logits<true><<<cdiv(E1N * NH, T), T>>>(p_el1, p_er1, e2p, p_ce, src1, dst1,
                                                p_elog, p_m, E1N);
    edge_exp<<<cdiv(E1N * NH, T), T>>>(p_m, dst1, p_elog, p_denom, E1N);
    edge_scatter<<<E1N, 64>>>(p_zs1, p_elog, p_denom, src1, dst1, p_agg, E1N);
    {
        dim3 g(HIDN / 128, cdiv(NPATH, 128));
        sgemm<2><<<g, T>>>(p_hp0, res_W1, p_hp1, NPATH, HIDN, 256, p_agg, nullptr);
    }

    // ================= conv 2: flow -> path =================
    attn_score<<<cdiv(NPATH * NH, T), T>>>(p_hp1, p_wr2, p_er2, NPATH);
    fill_kernel<<<cdiv(NPATH * NH, T), T>>>(p_m, -INFINITY, NPATH * NH);
    fill_kernel<<<cdiv(NPATH * NH, T), T>>>(p_denom, 0.0f, NPATH * NH);
    fill_kernel<<<cdiv(NPATH * HIDN, T), T>>>(p_agg, 0.0f, NPATH * HIDN);
    edge_logits<false><<<cdiv(E2N * NH, T), T>>>(p_el2, p_er2, nullptr, nullptr, src2, dst2,
                                                 p_elog, p_m, E2N);
    edge_exp<<<cdiv(E2N * NH, T), T>>>(p_m, dst2, p_elog, p_denom, E2N);
    edge_scatter<<<E2N, 64>>>(p_zs2, p_elog, p_denom, src2, dst2, p_agg, E2N);
    {
        dim3 g(HIDN / 128, cdiv(NPATH, 128));
        sgemm<2><<<g, T>>>(p_hp1, res_W2, p_hp2, NPATH, HIDN, 256, p_agg, nullptr);
    }

    // ================= decoder =================
    build_xcat<<<cdiv(NPATH * 2 * HIDN, T), T>>>(p_hp2, p_hp1, p_xcat);
    {
        dim3 g(HIDN / 128, cdiv(NPATH, 128));
        sgemm<3><<<g, T>>>(p_xcat, p_wcat, p_hidden, NPATH, HIDN, 512, nullptr, b1);
    }
    decoder_out<<<cdiv(NPATH * 32, T), T>>>(p_hidden, W2, b2, out);
}

// round 3
// speedup vs baseline: 1.9775x; 1.9775x over previous
#include <cuda_runtime.h>
#include <cmath>
#include <cstdint>

#define NLINK 2000
#define NFLOW 30000
#define NPATH 50000
#define E1N   120000
#define E2N   120000
#define HIDN  256
#define NH    4
#define HD    256

// ---------------- scratch (device globals; no allocation anywhere) ----------------
__device__ float g_h_link[NLINK * HIDN];
__device__ float g_h_flow[NFLOW * HIDN];
__device__ float g_h_path0[NPATH * HIDN];
__device__ float g_h_path1[NPATH * HIDN];
__device__ float g_h_path2[NPATH * HIDN];
__device__ float g_zs1[NLINK * NH * HD];
__device__ float g_zs2[NFLOW * NH * HD];
__device__ float g_el1[NLINK * NH];
__device__ float g_er1[NPATH * NH];
__device__ float g_el2[NFLOW * NH];
__device__ float g_er2[NPATH * NH];
__device__ float g_elog[E1N * NH];
__device__ float g_m[NPATH * NH];
__device__ float g_denom[NPATH * NH];
__device__ float g_agg[NPATH * HIDN];
__device__ float g_hidden[NPATH * HIDN];
__device__ float g_wl1[HIDN * NH];
__device__ float g_wr1[HIDN * NH];
__device__ float g_wl2[HIDN * NH];
__device__ float g_wr2[HIDN * NH];
__device__ float g_ce[NH];
__device__ float g_wcat[2 * HIDN * HIDN];

// ---------------- helpers ----------------
__device__ __forceinline__ void atomicMaxFloat(float* addr, float v) {
    if (v >= 0.0f) atomicMax((int*)addr, __float_as_int(v));
    else           atomicMin((unsigned int*)addr, __float_as_uint(v));
}

__device__ __forceinline__ uint32_t f2tf32(float f) {
    uint32_t r; asm("cvt.rna.tf32.f32 %0, %1;" : "=r"(r) : "f"(f)); return r;
}

__device__ __forceinline__ void mma_tf32(float* c, const uint32_t* a, const uint32_t* b) {
    asm volatile(
        "mma.sync.aligned.m16n8k8.row.col.f32.tf32.tf32.f32 "
        "{%0,%1,%2,%3}, {%4,%5,%6,%7}, {%8,%9}, {%0,%1,%2,%3};"
        : "+f"(c[0]), "+f"(c[1]), "+f"(c[2]), "+f"(c[3])
        : "r"(a[0]), "r"(a[1]), "r"(a[2]), "r"(a[3]), "r"(b[0]), "r"(b[1]));
}

// fill m=-inf, denom=0, agg=0 in one launch
__global__ void fill_conv_state(float* __restrict__ m, float* __restrict__ denom,
                                float* __restrict__ agg) {
    int i = blockIdx.x * blockDim.x + threadIdx.x;
    const int A = NPATH * NH;
    if (i < A) { m[i] = -INFINITY; denom[i] = 0.0f; }
    if (i < NPATH * HIDN) agg[i] = 0.0f;
}

// out[row*256+c] = relu(bias[c] + sum_k x[row*Kin+k]*W[k*256+c])
__global__ void proj_relu(const float* __restrict__ x, const float* __restrict__ W,
                          const float* __restrict__ b, float* __restrict__ out,
                          int M, int Kin) {
    int idx = blockIdx.x * blockDim.x + threadIdx.x;
    if (idx >= M * HIDN) return;
    int row = idx >> 8, c = idx & 255;
    float s = b[c];
    const float* xr = x + (size_t)row * Kin;
    for (int k = 0; k < Kin; ++k) s += xr[k] * W[k * HIDN + c];
    out[idx] = fmaxf(s, 0.0f);
}

// one warp per output; tasks 0..4095: wl1/wr1/wl2/wr2 folded weights; 4096..4099: ce
__global__ void attn_reduce_all(
    const float* __restrict__ fcA, const float* __restrict__ aA, float* __restrict__ oA,
    const float* __restrict__ fcB, const float* __restrict__ aB, float* __restrict__ oB,
    const float* __restrict__ fcC, const float* __restrict__ aC, float* __restrict__ oC,
    const float* __restrict__ fcD, const float* __restrict__ aD, float* __restrict__ oD,
    const float* __restrict__ fcE, const float* __restrict__ aE, float* __restrict__ oE) {
    int gw = (blockIdx.x * blockDim.x + threadIdx.x) >> 5;
    int lane = threadIdx.x & 31;
    if (gw >= 4100) return;
    const float *fc, *at; float* out; int foff, aoff, oidx;
    if (gw < 4096) {
        int sel = gw >> 10, t = gw & 1023;
        int k = t >> 2, h = t & 3;
        switch (sel) {
            case 0: fc = fcA; at = aA; out = oA; break;
            case 1: fc = fcB; at = aB; out = oB; break;
            case 2: fc = fcC; at = aC; out = oC; break;
            default: fc = fcD; at = aD; out = oD; break;
        }
        foff = k * (NH * HD) + h * HD; aoff = h * HD; oidx = t;
    } else {
        int h = gw - 4096;
        fc = fcE; at = aE; out = oE;
        foff = h * HD; aoff = h * HD; oidx = h;
    }
    float s = 0.0f;
    for (int d = lane; d < HD; d += 32) s += fc[foff + d] * at[aoff + d];
#pragma unroll
    for (int o = 16; o > 0; o >>= 1) s += __shfl_down_sync(0xffffffffu, s, o);
    if (lane == 0) out[oidx] = s;
}

// out[i*4+h] = sum_k hfeat[i*256+k] * w[k*4+h]
__global__ void attn_score(const float* __restrict__ hfeat, const float* __restrict__ w,
                           float* __restrict__ out, int M) {
    int idx = blockIdx.x * blockDim.x + threadIdx.x;
    if (idx >= M * NH) return;
    int i = idx >> 2, h = idx & 3;
    const float* row = hfeat + (size_t)i * HIDN;
    float s = 0.0f;
    for (int k = 0; k < HIDN; ++k) s += row[k] * w[k * NH + h];
    out[idx] = s;
}

template <bool HAS_EE>
__global__ void edge_logits(const float* __restrict__ el, const float* __restrict__ er,
                            const float* __restrict__ ef, const float* __restrict__ ce,
                            const int* __restrict__ src, const int* __restrict__ dst,
                            float* __restrict__ elog, float* __restrict__ m, int E) {
    int idx = blockIdx.x * blockDim.x + threadIdx.x;
    if (idx >= E * NH) return;
    int e = idx >> 2, h = idx & 3;
    float v = el[src[e] * NH + h] + er[dst[e] * NH + h];
    if (HAS_EE) v += ef[e] * ce[h];
    v = v > 0.0f ? v : 0.2f * v;
    elog[idx] = v;
    atomicMaxFloat(&m[dst[e] * NH + h], v);
}

__global__ void edge_exp(const float* __restrict__ mArr, const int* __restrict__ dst,
                         float* __restrict__ elog, float* __restrict__ denom, int E) {
    int idx = blockIdx.x * blockDim.x + threadIdx.x;
    if (idx >= E * NH) return;
    int e = idx >> 2, h = idx & 3;
    float a = expf(elog[idx] - mArr[dst[e] * NH + h]);
    elog[idx] = a;
    atomicAdd(&denom[dst[e] * NH + h], a);
}

__global__ void edge_scatter(const float* __restrict__ zs, const float* __restrict__ alog,
                             const float* __restrict__ denom,
                             const int* __restrict__ src, const int* __restrict__ dst,
                             float* __restrict__ agg, int E) {
    int e = blockIdx.x;
    if (e >= E) return;
    int t = threadIdx.x;  // 0..63
    int s = src[e], d = dst[e];
    float al[NH];
#pragma unroll
    for (int h = 0; h < NH; ++h)
        al[h] = 0.25f * alog[e * NH + h] / fmaxf(denom[d * NH + h], 1e-9f);
    const float4* z = (const float4*)(zs + (size_t)s * (NH * HD));
    float4 r = make_float4(0.f, 0.f, 0.f, 0.f);
#pragma unroll
    for (int h = 0; h < NH; ++h) {
        float4 zv = z[h * 64 + t];
        r.x += al[h] * zv.x; r.y += al[h] * zv.y;
        r.z += al[h] * zv.z; r.w += al[h] * zv.w;
    }
    float* outp = agg + (size_t)d * HIDN + t * 4;
    asm volatile("red.global.add.v4.f32 [%0], {%1,%2,%3,%4};"
                 :: "l"(outp), "f"(r.x), "f"(r.y), "f"(r.z), "f"(r.w) : "memory");
}

__global__ void build_wcat(const float* __restrict__ W1, float* __restrict__ wcat) {
    int idx = blockIdx.x * blockDim.x + threadIdx.x;
    if (idx >= 2 * HIDN * HIDN) return;
    int r = idx >> 8;
    wcat[idx] = (r < HIDN) ? (W1[idx] + W1[idx + 512 * HIDN]) : W1[idx];
}

__global__ void decoder_out(const float* __restrict__ hidden, const float* __restrict__ W2,
                            const float* __restrict__ b2, float* __restrict__ out) {
    int gw = (blockIdx.x * blockDim.x + threadIdx.x) >> 5;
    int lane = threadIdx.x & 31;
    if (gw >= NPATH) return;
    const float* hrow = hidden + (size_t)gw * HIDN;
    float s0 = 0.f, s1 = 0.f;
    for (int k = lane; k < HIDN; k += 32) {
        float hv = hrow[k];
        s0 += hv * W2[k * 2 + 0];
        s1 += hv * W2[k * 2 + 1];
    }
#pragma unroll
    for (int o = 16; o > 0; o >>= 1) {
        s0 += __shfl_down_sync(0xffffffffu, s0, o);
        s1 += __shfl_down_sync(0xffffffffu, s1, o);
    }
    if (lane == 0) {
        out[gw * 2 + 0] = s0 + b2[0];
        out[gw * 2 + 1] = s1 + b2[1];
    }
}

// ---------------- tf32 tensor-core GEMM ----------------
// C[M,N] = epi(A[M,K] @ B[K,N]); block tile 128x128, 8 warps of 64x32, BK=16.
// Requires N % 128 == 0, K % 16 == 0.
// EPI: 0 none, 2 relu(+add[M,N]), 3 relu(+bias[N]).
// SPLITA: A column k<256 reads A[row*256+k], else A2[row*256+k-256] (fused concat).
#define APAD 20
#define BPAD 136
template <int EPI, bool SPLITA>
__global__ __launch_bounds__(256)
void mm_tf32(const float* __restrict__ A, const float* __restrict__ A2,
             const float* __restrict__ B, float* __restrict__ C,
             int M, int N, int K,
             const float* __restrict__ add, const float* __restrict__ bias) {
    __shared__ uint32_t As[128][APAD];
    __shared__ uint32_t Bs[16][BPAD];
    const int tid = threadIdx.x;
    const int lane = tid & 31, wid = tid >> 5;
    const int g = lane >> 2, tig = lane & 3;
    const int warp_m = (wid >> 2) * 64, warp_n = (wid & 3) * 32;
    const int row0 = blockIdx.y * 128, col0 = blockIdx.x * 128;

    float acc[4][4][4];
#pragma unroll
    for (int i = 0; i < 4; ++i)
#pragma unroll
        for (int j = 0; j < 4; ++j)
#pragma unroll
            for (int r = 0; r < 4; ++r) acc[i][j][r] = 0.0f;

    // staging indices
    const int am[2] = { (tid + 0) >> 2, (tid + 256) >> 2 };           // 0..127
    const int ak = (tid & 3) << 2;                                     // 0,4,8,12
    const int bk[2] = { (tid + 0) >> 5, (tid + 256) >> 5 };           // 0..15
    const int bn = (tid & 31) << 2;                                    // 0..124

    float4 ar[2], br[2];
    auto load_tile = [&](int k0) {
#pragma unroll
        for (int p = 0; p < 2; ++p) {
            int r = row0 + am[p];
            int c = k0 + ak;
            float4 v = make_float4(0.f, 0.f, 0.f, 0.f);
            if (r < M) {
                if (SPLITA) {
                    const float* src = (c < HIDN) ? (A + (size_t)r * HIDN + c)
                                                  : (A2 + (size_t)r * HIDN + (c - HIDN));
                    v = *(const float4*)src;
                } else {
                    v = *(const float4*)(A + (size_t)r * K + c);
                }
            }
            ar[p] = v;
            br[p] = *(const float4*)(B + (size_t)(k0 + bk[p]) * N + col0 + bn);
        }
    };

    load_tile(0);
    for (int k0 = 0; k0 < K; k0 += 16) {
        __syncthreads();
#pragma unroll
        for (int p = 0; p < 2; ++p) {
            As[am[p]][ak + 0] = f2tf32(ar[p].x);
            As[am[p]][ak + 1] = f2tf32(ar[p].y);
            As[am[p]][ak + 2] = f2tf32(ar[p].z);
            As[am[p]][ak + 3] = f2tf32(ar[p].w);
            Bs[bk[p]][bn + 0] = f2tf32(br[p].x);
            Bs[bk[p]][bn + 1] = f2tf32(br[p].y);
            Bs[bk[p]][bn + 2] = f2tf32(br[p].z);
            Bs[bk[p]][bn + 3] = f2tf32(br[p].w);
        }
        __syncthreads();
        if (k0 + 16 < K) load_tile(k0 + 16);
#pragma unroll
        for (int ks = 0; ks < 2; ++ks) {
            const int kk = ks * 8;
            uint32_t af[4][4], bf[4][2];
#pragma unroll
            for (int mi = 0; mi < 4; ++mi) {
                int r = warp_m + 16 * mi + g;
                af[mi][0] = As[r][kk + tig];
                af[mi][1] = As[r + 8][kk + tig];
                af[mi][2] = As[r][kk + tig + 4];
                af[mi][3] = As[r + 8][kk + tig + 4];
            }
#pragma unroll
            for (int ni = 0; ni < 4; ++ni) {
                int c = warp_n + 8 * ni + g;
                bf[ni][0] = Bs[kk + tig][c];
                bf[ni][1] = Bs[kk + tig + 4][c];
            }
#pragma unroll
            for (int mi = 0; mi < 4; ++mi)
#pragma unroll
                for (int ni = 0; ni < 4; ++ni)
                    mma_tf32(acc[mi][ni], af[mi], bf[ni]);
        }
    }

    // epilogue
#pragma unroll
    for (int mi = 0; mi < 4; ++mi) {
#pragma unroll
        for (int ni = 0; ni < 4; ++ni) {
            int rA = row0 + warp_m + 16 * mi + g;
            int cA = col0 + warp_n + 8 * ni + 2 * tig;
#pragma unroll
            for (int half = 0; half < 2; ++half) {
                int r = rA + half * 8;
                if (r >= M) continue;
#pragma unroll
                for (int q = 0; q < 2; ++q) {
                    int c = cA + q;
                    float v = acc[mi][ni][half * 2 + q];
                    if (EPI == 2)      v = fmaxf(v + add[(size_t)r * N + c], 0.0f);
                    else if (EPI == 3) v = fmaxf(v + bias[c], 0.0f);
                    C[(size_t)r * N + c] = v;
                }
            }
        }
    }
}

// ---------------- host launch ----------------
static inline int cdiv(int a, int b) { return (a + b - 1) / b; }

extern "C" void kernel_launch(void* const* d_in, const int* in_sizes, int n_in,
                              void* d_out, int out_size) {
    (void)in_sizes; (void)n_in; (void)out_size;
    const float* x_link  = (const float*)d_in[0];
    const float* x_flow  = (const float*)d_in[1];
    const float* x_path  = (const float*)d_in[2];
    const float* e2p     = (const float*)d_in[3];
    const float* Wp_link = (const float*)d_in[4];
    const float* bp_link = (const float*)d_in[5];
    const float* Wp_flow = (const float*)d_in[6];
    const float* bp_flow = (const float*)d_in[7];
    const float* Wp_path = (const float*)d_in[8];
    const float* bp_path = (const float*)d_in[9];
    const float* fc_src1 = (const float*)d_in[10];
    const float* fc_dst1 = (const float*)d_in[11];
    const float* fc_e1   = (const float*)d_in[12];
    const float* attn_l1 = (const float*)d_in[13];
    const float* attn_r1 = (const float*)d_in[14];
    const float* attn_e1 = (const float*)d_in[15];
    const float* res_W1  = (const float*)d_in[16];
    const float* fc_src2 = (const float*)d_in[17];
    const float* fc_dst2 = (const float*)d_in[18];
    const float* attn_l2 = (const float*)d_in[19];
    const float* attn_r2 = (const float*)d_in[20];
    const float* res_W2  = (const float*)d_in[21];
    const float* W1      = (const float*)d_in[22];
    const float* b1      = (const float*)d_in[23];
    const float* W2      = (const float*)d_in[24];
    const float* b2      = (const float*)d_in[25];
    const int*   src1    = (const int*)d_in[26];
    const int*   dst1    = (const int*)d_in[27];
    const int*   src2    = (const int*)d_in[28];
    const int*   dst2    = (const int*)d_in[29];
    float* out = (float*)d_out;

#define SYM(p, s) float* p; cudaGetSymbolAddress((void**)&p, s)
    SYM(p_hlink, g_h_link);  SYM(p_hflow, g_h_flow);
    SYM(p_hp0, g_h_path0);   SYM(p_hp1, g_h_path1);   SYM(p_hp2, g_h_path2);
    SYM(p_zs1, g_zs1);       SYM(p_zs2, g_zs2);
    SYM(p_el1, g_el1);       SYM(p_er1, g_er1);
    SYM(p_el2, g_el2);       SYM(p_er2, g_er2);
    SYM(p_elog, g_elog);     SYM(p_m, g_m);           SYM(p_denom, g_denom);
    SYM(p_agg, g_agg);       SYM(p_hidden, g_hidden);
    SYM(p_wl1, g_wl1);       SYM(p_wr1, g_wr1);
    SYM(p_wl2, g_wl2);       SYM(p_wr2, g_wr2);
    SYM(p_ce, g_ce);         SYM(p_wcat, g_wcat);
#undef SYM

    const int T = 256;

    // --- folded weights (single fused launch) ---
    attn_reduce_all<<<cdiv(4100 * 32, T), T>>>(
        fc_src1, attn_l1, p_wl1,  fc_dst1, attn_r1, p_wr1,
        fc_src2, attn_l2, p_wl2,  fc_dst2, attn_r2, p_wr2,
        fc_e1, attn_e1, p_ce);
    build_wcat<<<cdiv(2 * HIDN * HIDN, T), T>>>(W1, p_wcat);

    // --- node projections ---
    proj_relu<<<cdiv(NLINK * HIDN, T), T>>>(x_link, Wp_link, bp_link, p_hlink, NLINK, 8);
    proj_relu<<<cdiv(NFLOW * HIDN, T), T>>>(x_flow, Wp_flow, bp_flow, p_hflow, NFLOW, 16);
    proj_relu<<<cdiv(NPATH * HIDN, T), T>>>(x_path, Wp_path, bp_path, p_hp0, NPATH, 8);

    // --- z_src GEMMs (tensor core) ---
    {
        dim3 g1(1024 / 128, cdiv(NLINK, 128));
        mm_tf32<0, false><<<g1, T>>>(p_hlink, nullptr, fc_src1, p_zs1,
                                     NLINK, 1024, 256, nullptr, nullptr);
        dim3 g2(1024 / 128, cdiv(NFLOW, 128));
        mm_tf32<0, false><<<g2, T>>>(p_hflow, nullptr, fc_src2, p_zs2,
                                     NFLOW, 1024, 256, nullptr, nullptr);
    }

    // --- attn scores (fp32) ---
    attn_score<<<cdiv(NLINK * NH, T), T>>>(p_hlink, p_wl1, p_el1, NLINK);
    attn_score<<<cdiv(NPATH * NH, T), T>>>(p_hp0, p_wr1, p_er1, NPATH);
    attn_score<<<cdiv(NFLOW * NH, T), T>>>(p_hflow, p_wl2, p_el2, NFLOW);

    // ================= conv 1: link -> path =================
    fill_conv_state<<<cdiv(NPATH * HIDN, T), T>>>(p_m, p_denom, p_agg);
    edge_logits<true><<<cdiv(E1N * NH, T), T>>>(p_el1, p_er1, e2p, p_ce, src1, dst1,
                                                p_elog, p_m, E1N);
    edge_exp<<<cdiv(E1N * NH, T), T>>>(p_m, dst1, p_elog, p_denom, E1N);
    edge_scatter<<<E1N, 64>>>(p_zs1, p_elog, p_denom, src1, dst1, p_agg, E1N);
    {
        dim3 g(HIDN / 128, cdiv(NPATH, 128));
        mm_tf32<2, false><<<g, T>>>(p_hp0, nullptr, res_W1, p_hp1,
                                    NPATH, HIDN, 256, p_agg, nullptr);
    }

    // ================= conv 2: flow -> path =================
    attn_score<<<cdiv(NPATH * NH, T), T>>>(p_hp1, p_wr2, p_er2, NPATH);
    fill_conv_state<<<cdiv(NPATH * HIDN, T), T>>>(p_m, p_denom, p_agg);
    edge_logits<false><<<cdiv(E2N * NH, T), T>>>(p_el2, p_er2, nullptr, nullptr, src2, dst2,
                                                 p_elog, p_m, E2N);
    edge_exp<<<cdiv(E2N * NH, T), T>>>(p_m, dst2, p_elog, p_denom, E2N);
    edge_scatter<<<E2N, 64>>>(p_zs2, p_elog, p_denom, src2, dst2, p_agg, E2N);
    {
        dim3 g(HIDN / 128, cdiv(NPATH, 128));
        mm_tf32<2, false><<<g, T>>>(p_hp1, nullptr, res_W2, p_hp2,
                                    NPATH, HIDN, 256, p_agg, nullptr);
    }

    // ================= decoder (concat fused via SPLITA) =================
    {
        dim3 g(HIDN / 128, cdiv(NPATH, 128));
        mm_tf32<3, true><<<g, T>>>(p_hp2, p_hp1, p_wcat, p_hidden,
                                   NPATH, HIDN, 512, nullptr, b1);
    }
    decoder_out<<<cdiv(NPATH * 32, T), T>>>(p_hidden, W2, b2, out);
}

// round 4
// speedup vs baseline: 2.4644x; 1.2462x over previous
#include <cuda_runtime.h>
#include <cmath>
#include <cstdint>

#define NLINK 2000
#define NFLOW 30000
#define NPATH 50000
#define E1N   120000
#define E2N   120000
#define HIDN  256
#define NH    4
#define HD    256

// ---------------- scratch (device globals; no allocation anywhere) ----------------
__device__ float g_h_link[NLINK * HIDN];
__device__ float g_h_flow[NFLOW * HIDN];
__device__ float g_h_path0[NPATH * HIDN];
__device__ float g_h_path1[NPATH * HIDN];
__device__ float g_h_path2[NPATH * HIDN];
__device__ float g_zs1[NLINK * NH * HD];
__device__ float g_zs2[NFLOW * NH * HD];
__device__ float g_el1[NLINK * NH];
__device__ float g_er1[NPATH * NH];
__device__ float g_el2[NFLOW * NH];
__device__ float g_er2[NPATH * NH];
__device__ float g_elog[E1N * NH];
__device__ float g_m[NPATH * NH];
__device__ float g_denom[NPATH * NH];
__device__ float g_agg[NPATH * HIDN];
__device__ float g_hidden[NPATH * HIDN];
__device__ float g_wl1[HIDN * NH];
__device__ float g_wr1[HIDN * NH];
__device__ float g_wl2[HIDN * NH];
__device__ float g_wr2[HIDN * NH];
__device__ float g_ce[NH];
__device__ float g_wcat[2 * HIDN * HIDN];

// ---------------- helpers ----------------
__device__ __forceinline__ void atomicMaxFloat(float* addr, float v) {
    if (v >= 0.0f) atomicMax((int*)addr, __float_as_int(v));
    else           atomicMin((unsigned int*)addr, __float_as_uint(v));
}

__device__ __forceinline__ uint32_t f2tf32(float f) {
    uint32_t r; asm("cvt.rna.tf32.f32 %0, %1;" : "=r"(r) : "f"(f)); return r;
}

__device__ __forceinline__ void mma_tf32(float* c, const uint32_t* a, const uint32_t* b) {
    asm volatile(
        "mma.sync.aligned.m16n8k8.row.col.f32.tf32.tf32.f32 "
        "{%0,%1,%2,%3}, {%4,%5,%6,%7}, {%8,%9}, {%0,%1,%2,%3};"
        : "+f"(c[0]), "+f"(c[1]), "+f"(c[2]), "+f"(c[3])
        : "r"(a[0]), "r"(a[1]), "r"(a[2]), "r"(a[3]), "r"(b[0]), "r"(b[1]));
}

// fill m=-inf, denom=0, agg=0 in one launch
__global__ void fill_conv_state(float* __restrict__ m, float* __restrict__ denom,
                                float* __restrict__ agg) {
    int i = blockIdx.x * blockDim.x + threadIdx.x;
    const int A = NPATH * NH;
    if (i < A) { m[i] = -INFINITY; denom[i] = 0.0f; }
    if (i < NPATH * HIDN) agg[i] = 0.0f;
}

// ---------------- proj_relu v2: 32 rows per block, W in regs, x in smem ----------------
template <int KIN>
__global__ __launch_bounds__(256)
void proj_relu(const float* __restrict__ x, const float* __restrict__ W,
               const float* __restrict__ b, float* __restrict__ out, int M) {
    __shared__ float xs[32][KIN];
    const int c = threadIdx.x;           // 0..255 = output column
    const int row0 = blockIdx.x * 32;
    // stage x rows
    for (int i = c; i < 32 * KIN; i += 256) {
        int r = i / KIN, k = i % KIN;
        xs[r][k] = (row0 + r < M) ? x[(size_t)(row0 + r) * KIN + k] : 0.0f;
    }
    float w[KIN];
#pragma unroll
    for (int k = 0; k < KIN; ++k) w[k] = W[k * HIDN + c];
    const float bias = b[c];
    __syncthreads();
    int rmax = min(32, M - row0);
    for (int r = 0; r < rmax; ++r) {
        float s = bias;
#pragma unroll
        for (int k = 0; k < KIN; ++k) s += xs[r][k] * w[k];
        out[(size_t)(row0 + r) * HIDN + c] = fmaxf(s, 0.0f);
    }
}

// one warp per output; tasks 0..4095: wl1/wr1/wl2/wr2 folded weights; 4096..4099: ce
__global__ void attn_reduce_all(
    const float* __restrict__ fcA, const float* __restrict__ aA, float* __restrict__ oA,
    const float* __restrict__ fcB, const float* __restrict__ aB, float* __restrict__ oB,
    const float* __restrict__ fcC, const float* __restrict__ aC, float* __restrict__ oC,
    const float* __restrict__ fcD, const float* __restrict__ aD, float* __restrict__ oD,
    const float* __restrict__ fcE, const float* __restrict__ aE, float* __restrict__ oE) {
    int gw = (blockIdx.x * blockDim.x + threadIdx.x) >> 5;
    int lane = threadIdx.x & 31;
    if (gw >= 4100) return;
    const float *fc, *at; float* out; int foff, aoff, oidx;
    if (gw < 4096) {
        int sel = gw >> 10, t = gw & 1023;
        int k = t >> 2, h = t & 3;
        switch (sel) {
            case 0: fc = fcA; at = aA; out = oA; break;
            case 1: fc = fcB; at = aB; out = oB; break;
            case 2: fc = fcC; at = aC; out = oC; break;
            default: fc = fcD; at = aD; out = oD; break;
        }
        foff = k * (NH * HD) + h * HD; aoff = h * HD; oidx = t;
    } else {
        int h = gw - 4096;
        fc = fcE; at = aE; out = oE;
        foff = h * HD; aoff = h * HD; oidx = h;
    }
    float s = 0.0f;
    for (int d = lane; d < HD; d += 32) s += fc[foff + d] * at[aoff + d];
#pragma unroll
    for (int o = 16; o > 0; o >>= 1) s += __shfl_down_sync(0xffffffffu, s, o);
    if (lane == 0) out[oidx] = s;
}

// ---------------- attn_score v2: one warp per row, all 4 heads at once ----------------
__global__ void attn_score(const float* __restrict__ hfeat, const float* __restrict__ w,
                           float* __restrict__ out, int M) {
    int gw = (blockIdx.x * blockDim.x + threadIdx.x) >> 5;
    int lane = threadIdx.x & 31;
    if (gw >= M) return;
    const float* row = hfeat + (size_t)gw * HIDN;
    float s0 = 0.f, s1 = 0.f, s2 = 0.f, s3 = 0.f;
#pragma unroll
    for (int j = 0; j < 8; ++j) {
        int k = lane + 32 * j;
        float xv = row[k];
        float4 wv = *(const float4*)(w + 4 * k);
        s0 += xv * wv.x; s1 += xv * wv.y; s2 += xv * wv.z; s3 += xv * wv.w;
    }
#pragma unroll
    for (int o = 16; o > 0; o >>= 1) {
        s0 += __shfl_down_sync(0xffffffffu, s0, o);
        s1 += __shfl_down_sync(0xffffffffu, s1, o);
        s2 += __shfl_down_sync(0xffffffffu, s2, o);
        s3 += __shfl_down_sync(0xffffffffu, s3, o);
    }
    if (lane == 0) *(float4*)(out + gw * 4) = make_float4(s0, s1, s2, s3);
}

// ---------------- per-edge (float4) logits / exp ----------------
template <bool HAS_EE>
__global__ void edge_logits(const float* __restrict__ el, const float* __restrict__ er,
                            const float* __restrict__ ef, const float* __restrict__ ce,
                            const int* __restrict__ src, const int* __restrict__ dst,
                            float* __restrict__ elog, float* __restrict__ m, int E) {
    int e = blockIdx.x * blockDim.x + threadIdx.x;
    if (e >= E) return;
    int s = src[e], d = dst[e];
    float4 a = *(const float4*)(el + s * 4);
    float4 b = *(const float4*)(er + d * 4);
    float v[4] = { a.x + b.x, a.y + b.y, a.z + b.z, a.w + b.w };
    if (HAS_EE) {
        float f = ef[e];
        float4 c = *(const float4*)ce;
        v[0] += f * c.x; v[1] += f * c.y; v[2] += f * c.z; v[3] += f * c.w;
    }
#pragma unroll
    for (int h = 0; h < 4; ++h) v[h] = v[h] > 0.0f ? v[h] : 0.2f * v[h];
    *(float4*)(elog + e * 4) = make_float4(v[0], v[1], v[2], v[3]);
#pragma unroll
    for (int h = 0; h < 4; ++h) atomicMaxFloat(&m[d * 4 + h], v[h]);
}

__global__ void edge_exp(const float* __restrict__ mArr, const int* __restrict__ dst,
                         float* __restrict__ elog, float* __restrict__ denom, int E) {
    int e = blockIdx.x * blockDim.x + threadIdx.x;
    if (e >= E) return;
    int d = dst[e];
    float4 v = *(const float4*)(elog + e * 4);
    float4 mv = *(const float4*)(mArr + d * 4);
    float a0 = __expf(v.x - mv.x), a1 = __expf(v.y - mv.y);
    float a2 = __expf(v.z - mv.z), a3 = __expf(v.w - mv.w);
    *(float4*)(elog + e * 4) = make_float4(a0, a1, a2, a3);
    atomicAdd(&denom[d * 4 + 0], a0);
    atomicAdd(&denom[d * 4 + 1], a1);
    atomicAdd(&denom[d * 4 + 2], a2);
    atomicAdd(&denom[d * 4 + 3], a3);
}

__global__ void edge_scatter(const float* __restrict__ zs, const float* __restrict__ alog,
                             const float* __restrict__ denom,
                             const int* __restrict__ src, const int* __restrict__ dst,
                             float* __restrict__ agg, int E) {
    int e = blockIdx.x;
    if (e >= E) return;
    int t = threadIdx.x;  // 0..63
    int s = src[e], d = dst[e];
    float al[NH];
    float4 av = *(const float4*)(alog + e * 4);
    float4 dv = *(const float4*)(denom + d * 4);
    al[0] = 0.25f * av.x / fmaxf(dv.x, 1e-9f);
    al[1] = 0.25f * av.y / fmaxf(dv.y, 1e-9f);
    al[2] = 0.25f * av.z / fmaxf(dv.z, 1e-9f);
    al[3] = 0.25f * av.w / fmaxf(dv.w, 1e-9f);
    const float4* z = (const float4*)(zs + (size_t)s * (NH * HD));
    float4 r = make_float4(0.f, 0.f, 0.f, 0.f);
#pragma unroll
    for (int h = 0; h < NH; ++h) {
        float4 zv = __ldg(&z[h * 64 + t]);
        r.x += al[h] * zv.x; r.y += al[h] * zv.y;
        r.z += al[h] * zv.z; r.w += al[h] * zv.w;
    }
    float* outp = agg + (size_t)d * HIDN + t * 4;
    asm volatile("red.global.add.v4.f32 [%0], {%1,%2,%3,%4};"
                 :: "l"(outp), "f"(r.x), "f"(r.y), "f"(r.z), "f"(r.w) : "memory");
}

__global__ void build_wcat(const float* __restrict__ W1, float* __restrict__ wcat) {
    int idx = blockIdx.x * blockDim.x + threadIdx.x;
    if (idx >= 2 * HIDN * HIDN) return;
    int r = idx >> 8;
    wcat[idx] = (r < HIDN) ? (W1[idx] + W1[idx + 512 * HIDN]) : W1[idx];
}

__global__ void decoder_out(const float* __restrict__ hidden, const float* __restrict__ W2,
                            const float* __restrict__ b2, float* __restrict__ out) {
    int gw = (blockIdx.x * blockDim.x + threadIdx.x) >> 5;
    int lane = threadIdx.x & 31;
    if (gw >= NPATH) return;
    const float* hrow = hidden + (size_t)gw * HIDN;
    float s0 = 0.f, s1 = 0.f;
#pragma unroll
    for (int j = 0; j < 8; ++j) {
        int k = lane + 32 * j;
        float hv = hrow[k];
        float2 wv = *(const float2*)(W2 + 2 * k);
        s0 += hv * wv.x;
        s1 += hv * wv.y;
    }
#pragma unroll
    for (int o = 16; o > 0; o >>= 1) {
        s0 += __shfl_down_sync(0xffffffffu, s0, o);
        s1 += __shfl_down_sync(0xffffffffu, s1, o);
    }
    if (lane == 0) *(float2*)(out + gw * 2) = make_float2(s0 + b2[0], s1 + b2[1]);
}

// ---------------- tf32 tensor-core GEMM ----------------
// C[M,N] = epi(A[M,K] @ B[K,N]); block tile 128x128, 8 warps of 64x32, BK=16.
// EPI: 0 none, 2 relu(+add[M,N]), 3 relu(+bias[N]).
// SPLITA: A column k<256 reads A, else A2 (fused concat).
#define APAD 20
#define BPAD 136
template <int EPI, bool SPLITA>
__global__ __launch_bounds__(256, 2)
void mm_tf32(const float* __restrict__ A, const float* __restrict__ A2,
             const float* __restrict__ B, float* __restrict__ C,
             int M, int N, int K,
             const float* __restrict__ add, const float* __restrict__ bias) {
    __shared__ uint32_t As[128][APAD];
    __shared__ uint32_t Bs[16][BPAD];
    const int tid = threadIdx.x;
    const int lane = tid & 31, wid = tid >> 5;
    const int g = lane >> 2, tig = lane & 3;
    const int warp_m = (wid >> 2) * 64, warp_n = (wid & 3) * 32;
    const int row0 = blockIdx.y * 128, col0 = blockIdx.x * 128;

    float acc[4][4][4];
#pragma unroll
    for (int i = 0; i < 4; ++i)
#pragma unroll
        for (int j = 0; j < 4; ++j)
#pragma unroll
            for (int r = 0; r < 4; ++r) acc[i][j][r] = 0.0f;

    const int am[2] = { (tid + 0) >> 2, (tid + 256) >> 2 };
    const int ak = (tid & 3) << 2;
    const int bk[2] = { (tid + 0) >> 5, (tid + 256) >> 5 };
    const int bn = (tid & 31) << 2;

    float4 ar[2], br[2];
    auto load_tile = [&](int k0) {
#pragma unroll
        for (int p = 0; p < 2; ++p) {
            int r = row0 + am[p];
            int c = k0 + ak;
            float4 v = make_float4(0.f, 0.f, 0.f, 0.f);
            if (r < M) {
                if (SPLITA) {
                    const float* src = (c < HIDN) ? (A + (size_t)r * HIDN + c)
                                                  : (A2 + (size_t)r * HIDN + (c - HIDN));
                    v = *(const float4*)src;
                } else {
                    v = *(const float4*)(A + (size_t)r * K + c);
                }
            }
            ar[p] = v;
            br[p] = *(const float4*)(B + (size_t)(k0 + bk[p]) * N + col0 + bn);
        }
    };

    load_tile(0);
    for (int k0 = 0; k0 < K; k0 += 16) {
        __syncthreads();
#pragma unroll
        for (int p = 0; p < 2; ++p) {
            As[am[p]][ak + 0] = f2tf32(ar[p].x);
            As[am[p]][ak + 1] = f2tf32(ar[p].y);
            As[am[p]][ak + 2] = f2tf32(ar[p].z);
            As[am[p]][ak + 3] = f2tf32(ar[p].w);
            Bs[bk[p]][bn + 0] = f2tf32(br[p].x);
            Bs[bk[p]][bn + 1] = f2tf32(br[p].y);
            Bs[bk[p]][bn + 2] = f2tf32(br[p].z);
            Bs[bk[p]][bn + 3] = f2tf32(br[p].w);
        }
        __syncthreads();
        if (k0 + 16 < K) load_tile(k0 + 16);
#pragma unroll
        for (int ks = 0; ks < 2; ++ks) {
            const int kk = ks * 8;
            uint32_t af[4][4], bf[4][2];
#pragma unroll
            for (int mi = 0; mi < 4; ++mi) {
                int r = warp_m + 16 * mi + g;
                af[mi][0] = As[r][kk + tig];
                af[mi][1] = As[r + 8][kk + tig];
                af[mi][2] = As[r][kk + tig + 4];
                af[mi][3] = As[r + 8][kk + tig + 4];
            }
#pragma unroll
            for (int ni = 0; ni < 4; ++ni) {
                int c = warp_n + 8 * ni + g;
                bf[ni][0] = Bs[kk + tig][c];
                bf[ni][1] = Bs[kk + tig + 4][c];
            }
#pragma unroll
            for (int mi = 0; mi < 4; ++mi)
#pragma unroll
                for (int ni = 0; ni < 4; ++ni)
                    mma_tf32(acc[mi][ni], af[mi], bf[ni]);
        }
    }

#pragma unroll
    for (int mi = 0; mi < 4; ++mi) {
#pragma unroll
        for (int ni = 0; ni < 4; ++ni) {
            int rA = row0 + warp_m + 16 * mi + g;
            int cA = col0 + warp_n + 8 * ni + 2 * tig;
#pragma unroll
            for (int half = 0; half < 2; ++half) {
                int r = rA + half * 8;
                if (r >= M) continue;
#pragma unroll
                for (int q = 0; q < 2; ++q) {
                    int c = cA + q;
                    float v = acc[mi][ni][half * 2 + q];
                    if (EPI == 2)      v = fmaxf(v + add[(size_t)r * N + c], 0.0f);
                    else if (EPI == 3) v = fmaxf(v + bias[c], 0.0f);
                    C[(size_t)r * N + c] = v;
                }
            }
        }
    }
}

// ---------------- host launch ----------------
static inline int cdiv(int a, int b) { return (a + b - 1) / b; }

extern "C" void kernel_launch(void* const* d_in, const int* in_sizes, int n_in,
                              void* d_out, int out_size) {
    (void)in_sizes; (void)n_in; (void)out_size;
    const float* x_link  = (const float*)d_in[0];
    const float* x_flow  = (const float*)d_in[1];
    const float* x_path  = (const float*)d_in[2];
    const float* e2p     = (const float*)d_in[3];
    const float* Wp_link = (const float*)d_in[4];
    const float* bp_link = (const float*)d_in[5];
    const float* Wp_flow = (const float*)d_in[6];
    const float* bp_flow = (const float*)d_in[7];
    const float* Wp_path = (const float*)d_in[8];
    const float* bp_path = (const float*)d_in[9];
    const float* fc_src1 = (const float*)d_in[10];
    const float* fc_dst1 = (const float*)d_in[11];
    const float* fc_e1   = (const float*)d_in[12];
    const float* attn_l1 = (const float*)d_in[13];
    const float* attn_r1 = (const float*)d_in[14];
    const float* attn_e1 = (const float*)d_in[15];
    const float* res_W1  = (const float*)d_in[16];
    const float* fc_src2 = (const float*)d_in[17];
    const float* fc_dst2 = (const float*)d_in[18];
    const float* attn_l2 = (const float*)d_in[19];
    const float* attn_r2 = (const float*)d_in[20];
    const float* res_W2  = (const float*)d_in[21];
    const float* W1      = (const float*)d_in[22];
    const float* b1      = (const float*)d_in[23];
    const float* W2      = (const float*)d_in[24];
    const float* b2      = (const float*)d_in[25];
    const int*   src1    = (const int*)d_in[26];
    const int*   dst1    = (const int*)d_in[27];
    const int*   src2    = (const int*)d_in[28];
    const int*   dst2    = (const int*)d_in[29];
    float* out = (float*)d_out;

#define SYM(p, s) float* p; cudaGetSymbolAddress((void**)&p, s)
    SYM(p_hlink, g_h_link);  SYM(p_hflow, g_h_flow);
    SYM(p_hp0, g_h_path0);   SYM(p_hp1, g_h_path1);   SYM(p_hp2, g_h_path2);
    SYM(p_zs1, g_zs1);       SYM(p_zs2, g_zs2);
    SYM(p_el1, g_el1);       SYM(p_er1, g_er1);
    SYM(p_el2, g_el2);       SYM(p_er2, g_er2);
    SYM(p_elog, g_elog);     SYM(p_m, g_m);           SYM(p_denom, g_denom);
    SYM(p_agg, g_agg);       SYM(p_hidden, g_hidden);
    SYM(p_wl1, g_wl1);       SYM(p_wr1, g_wr1);
    SYM(p_wl2, g_wl2);       SYM(p_wr2, g_wr2);
    SYM(p_ce, g_ce);         SYM(p_wcat, g_wcat);
#undef SYM

    const int T = 256;

    // --- folded weights ---
    attn_reduce_all<<<cdiv(4100 * 32, T), T>>>(
        fc_src1, attn_l1, p_wl1,  fc_dst1, attn_r1, p_wr1,
        fc_src2, attn_l2, p_wl2,  fc_dst2, attn_r2, p_wr2,
        fc_e1, attn_e1, p_ce);
    build_wcat<<<cdiv(2 * HIDN * HIDN, T), T>>>(W1, p_wcat);

    // --- node projections ---
    proj_relu<8><<<cdiv(NLINK, 32), T>>>(x_link, Wp_link, bp_link, p_hlink, NLINK);
    proj_relu<16><<<cdiv(NFLOW, 32), T>>>(x_flow, Wp_flow, bp_flow, p_hflow, NFLOW);
    proj_relu<8><<<cdiv(NPATH, 32), T>>>(x_path, Wp_path, bp_path, p_hp0, NPATH);

    // --- z_src GEMMs (tensor core) ---
    {
        dim3 g1(1024 / 128, cdiv(NLINK, 128));
        mm_tf32<0, false><<<g1, T>>>(p_hlink, nullptr, fc_src1, p_zs1,
                                     NLINK, 1024, 256, nullptr, nullptr);
        dim3 g2(1024 / 128, cdiv(NFLOW, 128));
        mm_tf32<0, false><<<g2, T>>>(p_hflow, nullptr, fc_src2, p_zs2,
                                     NFLOW, 1024, 256, nullptr, nullptr);
    }

    // --- attn scores (warp per row) ---
    attn_score<<<cdiv(NLINK * 32, T), T>>>(p_hlink, p_wl1, p_el1, NLINK);
    attn_score<<<cdiv(NPATH * 32, T), T>>>(p_hp0, p_wr1, p_er1, NPATH);
    attn_score<<<cdiv(NFLOW * 32, T), T>>>(p_hflow, p_wl2, p_el2, NFLOW);

    // ================= conv 1: link -> path =================
    fill_conv_state<<<cdiv(NPATH * HIDN, T), T>>>(p_m, p_denom, p_agg);
    edge_logits<true><<<cdiv(E1N, T), T>>>(p_el1, p_er1, e2p, p_ce, src1, dst1,
                                           p_elog, p_m, E1N);
    edge_exp<<<cdiv(E1N, T), T>>>(p_m, dst1, p_elog, p_denom, E1N);
    edge_scatter<<<E1N, 64>>>(p_zs1, p_elog, p_denom, src1, dst1, p_agg, E1N);
    {
        dim3 g(HIDN / 128, cdiv(NPATH, 128));
        mm_tf32<2, false><<<g, T>>>(p_hp0, nullptr, res_W1, p_hp1,
                                    NPATH, HIDN, 256, p_agg, nullptr);
    }

    // ================= conv 2: flow -> path =================
    attn_score<<<cdiv(NPATH * 32, T), T>>>(p_hp1, p_wr2, p_er2, NPATH);
    fill_conv_state<<<cdiv(NPATH * HIDN, T), T>>>(p_m, p_denom, p_agg);
    edge_logits<false><<<cdiv(E2N, T), T>>>(p_el2, p_er2, nullptr, nullptr, src2, dst2,
                                            p_elog, p_m, E2N);
    edge_exp<<<cdiv(E2N, T), T>>>(p_m, dst2, p_elog, p_denom, E2N);
    edge_scatter<<<E2N, 64>>>(p_zs2, p_elog, p_denom, src2, dst2, p_agg, E2N);
    {
        dim3 g(HIDN / 128, cdiv(NPATH, 128));
        mm_tf32<2, false><<<g, T>>>(p_hp1, nullptr, res_W2, p_hp2,
                                    NPATH, HIDN, 256, p_agg, nullptr);
    }

    // ================= decoder (concat fused via SPLITA) =================
    {
        dim3 g(HIDN / 128, cdiv(NPATH, 128));
        mm_tf32<3, true><<<g, T>>>(p_hp2, p_hp1, p_wcat, p_hidden,
                                   NPATH, HIDN, 512, nullptr, b1);
    }
    decoder_out<<<cdiv(NPATH * 32, T), T>>>(p_hidden, W2, b2, out);
}

// round 6
// speedup vs baseline: 2.7267x; 1.1064x over previous
#include <cuda_runtime.h>
#include <cuda_fp16.h>
#include <cmath>
#include <cstdint>

#define NLINK 2000
#define NFLOW 30000
#define NPATH 50000
#define E1N   120000
#define E2N   120000
#define HIDN  256
#define NH    4
#define HD    256

// ---------------- scratch ----------------
__device__ float  g_h_link[NLINK * HIDN];
__device__ float  g_h_flow[NFLOW * HIDN];
__device__ float  g_h_path0[NPATH * HIDN];
__device__ float  g_h_path1[NPATH * HIDN];
__device__ float  g_h_path2[NPATH * HIDN];
__device__ __half g_zs1[NLINK * NH * HD];
__device__ __half g_zs2[NFLOW * NH * HD];
__device__ float  g_el1[NLINK * NH];
__device__ float  g_er1[NPATH * NH];
__device__ float  g_el2[NFLOW * NH];
__device__ float  g_er2[NPATH * NH];
__device__ float  g_ea[E1N * NH];       // exp(e) per edge
__device__ float  g_denom[NPATH * NH];
__device__ float  g_agg[NPATH * HIDN];
__device__ float  g_hidden[NPATH * HIDN];
__device__ float  g_wl1[HIDN * NH];
__device__ float  g_wr1[HIDN * NH];
__device__ float  g_wl2[HIDN * NH];
__device__ float  g_wr2[HIDN * NH];
__device__ float  g_ce[NH];
__device__ float  g_wcat[2 * HIDN * HIDN];
// tf32-rounded weight copies
__device__ float  g_fc1c[HIDN * NH * HD];
__device__ float  g_fc2c[HIDN * NH * HD];
__device__ float  g_rw1c[HIDN * HIDN];
__device__ float  g_rw2c[HIDN * HIDN];

// ---------------- helpers ----------------
__device__ __forceinline__ uint32_t f2tf32(float f) {
    uint32_t r; asm("cvt.rna.tf32.f32 %0, %1;" : "=r"(r) : "f"(f)); return r;
}
__device__ __forceinline__ float rna32(float f) { return __uint_as_float(f2tf32(f)); }

__device__ __forceinline__ void mma_tf32(float* c, const uint32_t* a, const uint32_t* b) {
    asm volatile(
        "mma.sync.aligned.m16n8k8.row.col.f32.tf32.tf32.f32 "
        "{%0,%1,%2,%3}, {%4,%5,%6,%7}, {%8,%9}, {%0,%1,%2,%3};"
        : "+f"(c[0]), "+f"(c[1]), "+f"(c[2]), "+f"(c[3])
        : "r"(a[0]), "r"(a[1]), "r"(a[2]), "r"(a[3]), "r"(b[0]), "r"(b[1]));
}

__device__ __forceinline__ void cp16(uint32_t saddr, const void* gaddr, int szbytes) {
    asm volatile("cp.async.cg.shared.global [%0], [%1], 16, %2;\n"
                 :: "r"(saddr), "l"(gaddr), "r"(szbytes));
}
__device__ __forceinline__ void cp_commit() { asm volatile("cp.async.commit_group;\n"); }
template <int W>
__device__ __forceinline__ void cp_wait() { asm volatile("cp.async.wait_group %0;\n" :: "n"(W)); }

// fill denom=0, agg=0
__global__ void fill_conv_state(float* __restrict__ denom, float* __restrict__ agg) {
    int i = blockIdx.x * blockDim.x + threadIdx.x;
    if (i < NPATH * NH) denom[i] = 0.0f;
    if (i < NPATH * HIDN) agg[i] = 0.0f;
}

// rna-convert the four weight matrices into scratch copies
__global__ void cvt_weights(const float* __restrict__ fc1, const float* __restrict__ fc2,
                            const float* __restrict__ rw1, const float* __restrict__ rw2,
                            float* __restrict__ o1, float* __restrict__ o2,
                            float* __restrict__ o3, float* __restrict__ o4) {
    int i = blockIdx.x * blockDim.x + threadIdx.x;
    const int NW = HIDN * NH * HD;          // 262144
    const int NR = HIDN * HIDN;             // 65536
    if (i < NW) { o1[i] = rna32(fc1[i]); o2[i] = rna32(fc2[i]); }
    if (i < NR) { o3[i] = rna32(rw1[i]); o4[i] = rna32(rw2[i]); }
}

// ---------------- proj_relu: 32 rows/block, W in regs, x in smem; tf32-rounded out ----------------
template <int KIN>
__global__ __launch_bounds__(256)
void proj_relu(const float* __restrict__ x, const float* __restrict__ W,
               const float* __restrict__ b, float* __restrict__ out, int M) {
    __shared__ float xs[32][KIN];
    const int c = threadIdx.x;
    const int row0 = blockIdx.x * 32;
    for (int i = c; i < 32 * KIN; i += 256) {
        int r = i / KIN, k = i % KIN;
        xs[r][k] = (row0 + r < M) ? x[(size_t)(row0 + r) * KIN + k] : 0.0f;
    }
    float w[KIN];
#pragma unroll
    for (int k = 0; k < KIN; ++k) w[k] = W[k * HIDN + c];
    const float bias = b[c];
    __syncthreads();
    int rmax = min(32, M - row0);
    for (int r = 0; r < rmax; ++r) {
        float s = bias;
#pragma unroll
        for (int k = 0; k < KIN; ++k) s += xs[r][k] * w[k];
        out[(size_t)(row0 + r) * HIDN + c] = rna32(fmaxf(s, 0.0f));
    }
}

// one warp per output; 0..4095: wl1/wr1/wl2/wr2; 4096..4099: ce
__global__ void attn_reduce_all(
    const float* __restrict__ fcA, const float* __restrict__ aA, float* __restrict__ oA,
    const float* __restrict__ fcB, const float* __restrict__ aB, float* __restrict__ oB,
    const float* __restrict__ fcC, const float* __restrict__ aC, float* __restrict__ oC,
    const float* __restrict__ fcD, const float* __restrict__ aD, float* __restrict__ oD,
    const float* __restrict__ fcE, const float* __restrict__ aE, float* __restrict__ oE) {
    int gw = (blockIdx.x * blockDim.x + threadIdx.x) >> 5;
    int lane = threadIdx.x & 31;
    if (gw >= 4100) return;
    const float *fc, *at; float* out; int foff, aoff, oidx;
    if (gw < 4096) {
        int sel = gw >> 10, t = gw & 1023;
        int k = t >> 2, h = t & 3;
        switch (sel) {
            case 0: fc = fcA; at = aA; out = oA; break;
            case 1: fc = fcB; at = aB; out = oB; break;
            case 2: fc = fcC; at = aC; out = oC; break;
            default: fc = fcD; at = aD; out = oD; break;
        }
        foff = k * (NH * HD) + h * HD; aoff = h * HD; oidx = t;
    } else {
        int h = gw - 4096;
        fc = fcE; at = aE; out = oE;
        foff = h * HD; aoff = h * HD; oidx = h;
    }
    float s = 0.0f;
    for (int d = lane; d < HD; d += 32) s += fc[foff + d] * at[aoff + d];
#pragma unroll
    for (int o = 16; o > 0; o >>= 1) s += __shfl_down_sync(0xffffffffu, s, o);
    if (lane == 0) out[oidx] = s;
}

// ---------------- attn_score: one warp per row ----------------
__global__ void attn_score(const float* __restrict__ hfeat, const float* __restrict__ w,
                           float* __restrict__ out, int M) {
    int gw = (blockIdx.x * blockDim.x + threadIdx.x) >> 5;
    int lane = threadIdx.x & 31;
    if (gw >= M) return;
    const float* row = hfeat + (size_t)gw * HIDN;
    float s0 = 0.f, s1 = 0.f, s2 = 0.f, s3 = 0.f;
#pragma unroll
    for (int j = 0; j < 8; ++j) {
        int k = lane + 32 * j;
        float xv = row[k];
        float4 wv = *(const float4*)(w + 4 * k);
        s0 += xv * wv.x; s1 += xv * wv.y; s2 += xv * wv.z; s3 += xv * wv.w;
    }
#pragma unroll
    for (int o = 16; o > 0; o >>= 1) {
        s0 += __shfl_down_sync(0xffffffffu, s0, o);
        s1 += __shfl_down_sync(0xffffffffu, s1, o);
        s2 += __shfl_down_sync(0xffffffffu, s2, o);
        s3 += __shfl_down_sync(0xffffffffu, s3, o);
    }
    if (lane == 0) *(float4*)(out + gw * 4) = make_float4(s0, s1, s2, s3);
}

// ---------------- fused edge softmax (no max-shift; softmax is shift-invariant and
// logits are O(1) here, so exp cannot overflow) ----------------
template <bool HAS_EE>
__global__ void edge_softmax(const float* __restrict__ el, const float* __restrict__ er,
                             const float* __restrict__ ef, const float* __restrict__ ce,
                             const int* __restrict__ src, const int* __restrict__ dst,
                             float* __restrict__ a_out, float* __restrict__ denom, int E) {
    int e = blockIdx.x * blockDim.x + threadIdx.x;
    if (e >= E) return;
    int s = src[e], d = dst[e];
    float4 a = *(const float4*)(el + s * 4);
    float4 b = *(const float4*)(er + d * 4);
    float v[4] = { a.x + b.x, a.y + b.y, a.z + b.z, a.w + b.w };
    if (HAS_EE) {
        float f = ef[e];
        float4 c = *(const float4*)ce;
        v[0] += f * c.x; v[1] += f * c.y; v[2] += f * c.z; v[3] += f * c.w;
    }
#pragma unroll
    for (int h = 0; h < 4; ++h) {
        float lv = v[h] > 0.0f ? v[h] : 0.2f * v[h];
        v[h] = __expf(lv);
    }
    *(float4*)(a_out + e * 4) = make_float4(v[0], v[1], v[2], v[3]);
    atomicAdd(&denom[d * 4 + 0], v[0]);
    atomicAdd(&denom[d * 4 + 1], v[1]);
    atomicAdd(&denom[d * 4 + 2], v[2]);
    atomicAdd(&denom[d * 4 + 3], v[3]);
}

// ---------------- edge scatter with fp16 z ----------------
__global__ void edge_scatter(const __half* __restrict__ zs, const float* __restrict__ a_in,
                             const float* __restrict__ denom,
                             const int* __restrict__ src, const int* __restrict__ dst,
                             float* __restrict__ agg, int E) {
    int e = blockIdx.x;
    if (e >= E) return;
    int t = threadIdx.x;  // 0..63
    int s = src[e], d = dst[e];
    float al[NH];
    float4 av = *(const float4*)(a_in + e * 4);
    float4 dv = *(const float4*)(denom + d * 4);
    al[0] = 0.25f * av.x / fmaxf(dv.x, 1e-9f);
    al[1] = 0.25f * av.y / fmaxf(dv.y, 1e-9f);
    al[2] = 0.25f * av.z / fmaxf(dv.z, 1e-9f);
    al[3] = 0.25f * av.w / fmaxf(dv.w, 1e-9f);
    const uint2* z = (const uint2*)(zs + (size_t)s * (NH * HD));  // uint2 = 4 halves
    float4 r = make_float4(0.f, 0.f, 0.f, 0.f);
#pragma unroll
    for (int h = 0; h < NH; ++h) {
        uint2 u = __ldg(&z[h * 64 + t]);
        float2 f0 = __half22float2(*(const __half2*)&u.x);
        float2 f1 = __half22float2(*(const __half2*)&u.y);
        r.x += al[h] * f0.x; r.y += al[h] * f0.y;
        r.z += al[h] * f1.x; r.w += al[h] * f1.y;
    }
    float* outp = agg + (size_t)d * HIDN + t * 4;
    asm volatile("red.global.add.v4.f32 [%0], {%1,%2,%3,%4};"
                 :: "l"(outp), "f"(r.x), "f"(r.y), "f"(r.z), "f"(r.w) : "memory");
}

__global__ void build_wcat(const float* __restrict__ W1, float* __restrict__ wcat) {
    int idx = blockIdx.x * blockDim.x + threadIdx.x;
    if (idx >= 2 * HIDN * HIDN) return;
    int r = idx >> 8;
    wcat[idx] = rna32((r < HIDN) ? (W1[idx] + W1[idx + 512 * HIDN]) : W1[idx]);
}

__global__ void decoder_out(const float* __restrict__ hidden, const float* __restrict__ W2,
                            const float* __restrict__ b2, float* __restrict__ out) {
    int gw = (blockIdx.x * blockDim.x + threadIdx.x) >> 5;
    int lane = threadIdx.x & 31;
    if (gw >= NPATH) return;
    const float* hrow = hidden + (size_t)gw * HIDN;
    float s0 = 0.f, s1 = 0.f;
#pragma unroll
    for (int j = 0; j < 8; ++j) {
        int k = lane + 32 * j;
        float hv = hrow[k];
        float2 wv = *(const float2*)(W2 + 2 * k);
        s0 += hv * wv.x;
        s1 += hv * wv.y;
    }
#pragma unroll
    for (int o = 16; o > 0; o >>= 1) {
        s0 += __shfl_down_sync(0xffffffffu, s0, o);
        s1 += __shfl_down_sync(0xffffffffu, s1, o);
    }
    if (lane == 0) *(float2*)(out + gw * 2) = make_float2(s0 + b2[0], s1 + b2[1]);
}

// ---------------- tf32 tensor-core GEMM, cp.async 2-stage pipeline ----------------
// All inputs are PRE-ROUNDED to tf32 (rna) by their producers; smem gets raw 16B copies.
// C[M,N] = epi(A[M,K] @ B[K,N]); block 128x128, 8 warps (2x4) of 64x32, BK=16.
// EPI: 0 = fp32 out, 1 = fp16 out, 2 = rna(relu(+add[M,N])) fp32, 3 = relu(+bias[N]) fp32.
// SPLITA: A col k<256 from A, else A2 (fused concat).
template <int EPI, bool SPLITA>
__global__ __launch_bounds__(256, 2)
void mm_tf32(const float* __restrict__ A, const float* __restrict__ A2,
             const float* __restrict__ B, void* __restrict__ Cout,
             int M, int N, int K,
             const float* __restrict__ add, const float* __restrict__ bias) {
    __shared__ uint32_t As[2][128][20];
    __shared__ uint32_t Bs[2][16][136];
    const int tid = threadIdx.x;
    const int lane = tid & 31, wid = tid >> 5;
    const int g = lane >> 2, tig = lane & 3;
    const int warp_m = (wid >> 2) * 64, warp_n = (wid & 3) * 32;
    const int row0 = blockIdx.y * 128, col0 = blockIdx.x * 128;

    float acc[4][4][4];
#pragma unroll
    for (int i = 0; i < 4; ++i)
#pragma unroll
        for (int j = 0; j < 4; ++j)
#pragma unroll
            for (int r = 0; r < 4; ++r) acc[i][j][r] = 0.0f;

    const int am[2] = { (tid + 0) >> 2, (tid + 256) >> 2 };
    const int ak = (tid & 3) << 2;
    const int bk[2] = { (tid + 0) >> 5, (tid + 256) >> 5 };
    const int bn = (tid & 31) << 2;

    auto issue = [&](int st, int k0) {
#pragma unroll
        for (int p = 0; p < 2; ++p) {
            int r = row0 + am[p];
            int c = k0 + ak;
            const float* asrc;
            if (r < M) {
                if (SPLITA) asrc = (c < HIDN) ? (A + (size_t)r * HIDN + c)
                                              : (A2 + (size_t)r * HIDN + (c - HIDN));
                else        asrc = A + (size_t)r * K + c;
            } else asrc = A;  // safe address; src-size 0 => zero-fill
            cp16((uint32_t)__cvta_generic_to_shared(&As[st][am[p]][ak]), asrc,
                 r < M ? 16 : 0);
            const float* bsrc = B + (size_t)(k0 + bk[p]) * N + col0 + bn;
            cp16((uint32_t)__cvta_generic_to_shared(&Bs[st][bk[p]][bn]), bsrc, 16);
        }
        cp_commit();
    };

    const int nIter = K / 16;
    issue(0, 0);
    for (int it = 0; it < nIter; ++it) {
        if (it + 1 < nIter) {
            issue((it + 1) & 1, (it + 1) * 16);
            cp_wait<1>();
        } else {
            cp_wait<0>();
        }
        __syncthreads();
        const int st = it & 1;
#pragma unroll
        for (int ks = 0; ks < 2; ++ks) {
            const int kk = ks * 8;
            uint32_t af[4][4], bf[4][2];
#pragma unroll
            for (int mi = 0; mi < 4; ++mi) {
                int r = warp_m + 16 * mi + g;
                af[mi][0] = As[st][r][kk + tig];
                af[mi][1] = As[st][r + 8][kk + tig];
                af[mi][2] = As[st][r][kk + tig + 4];
                af[mi][3] = As[st][r + 8][kk + tig + 4];
            }
#pragma unroll
            for (int ni = 0; ni < 4; ++ni) {
                int c = warp_n + 8 * ni + g;
                bf[ni][0] = Bs[st][kk + tig][c];
                bf[ni][1] = Bs[st][kk + tig + 4][c];
            }
#pragma unroll
            for (int mi = 0; mi < 4; ++mi)
#pragma unroll
                for (int ni = 0; ni < 4; ++ni)
                    mma_tf32(acc[mi][ni], af[mi], bf[ni]);
        }
        __syncthreads();
    }

#pragma unroll
    for (int mi = 0; mi < 4; ++mi) {
#pragma unroll
        for (int ni = 0; ni < 4; ++ni) {
            int rA = row0 + warp_m + 16 * mi + g;
            int cA = col0 + warp_n + 8 * ni + 2 * tig;
#pragma unroll
            for (int half_ = 0; half_ < 2; ++half_) {
                int r = rA + half_ * 8;
                if (r >= M) continue;
                float v0 = acc[mi][ni][half_ * 2 + 0];
                float v1 = acc[mi][ni][half_ * 2 + 1];
                if (EPI == 1) {
                    __half2* C = (__half2*)Cout;
                    C[((size_t)r * N + cA) >> 1] = __floats2half2_rn(v0, v1);
                } else {
                    float* C = (float*)Cout;
                    if (EPI == 2) {
                        v0 = rna32(fmaxf(v0 + add[(size_t)r * N + cA + 0], 0.0f));
                        v1 = rna32(fmaxf(v1 + add[(size_t)r * N + cA + 1], 0.0f));
                    } else if (EPI == 3) {
                        v0 = fmaxf(v0 + bias[cA + 0], 0.0f);
                        v1 = fmaxf(v1 + bias[cA + 1], 0.0f);
                    }
                    C[(size_t)r * N + cA + 0] = v0;
                    C[(size_t)r * N + cA + 1] = v1;
                }
            }
        }
    }
}

// ---------------- host launch ----------------
static inline int cdiv(int a, int b) { return (a + b - 1) / b; }

extern "C" void kernel_launch(void* const* d_in, const int* in_sizes, int n_in,
                              void* d_out, int out_size) {
    (void)in_sizes; (void)n_in; (void)out_size;
    const float* x_link  = (const float*)d_in[0];
    const float* x_flow  = (const float*)d_in[1];
    const float* x_path  = (const float*)d_in[2];
    const float* e2p     = (const float*)d_in[3];
    const float* Wp_link = (const float*)d_in[4];
    const float* bp_link = (const float*)d_in[5];
    const float* Wp_flow = (const float*)d_in[6];
    const float* bp_flow = (const float*)d_in[7];
    const float* Wp_path = (const float*)d_in[8];
    const float* bp_path = (const float*)d_in[9];
    const float* fc_src1 = (const float*)d_in[10];
    const float* fc_dst1 = (const float*)d_in[11];
    const float* fc_e1   = (const float*)d_in[12];
    const float* attn_l1 = (const float*)d_in[13];
    const float* attn_r1 = (const float*)d_in[14];
    const float* attn_e1 = (const float*)d_in[15];
    const float* res_W1  = (const float*)d_in[16];
    const float* fc_src2 = (const float*)d_in[17];
    const float* fc_dst2 = (const float*)d_in[18];
    const float* attn_l2 = (const float*)d_in[19];
    const float* attn_r2 = (const float*)d_in[20];
    const float* res_W2  = (const float*)d_in[21];
    const float* W1      = (const float*)d_in[22];
    const float* b1      = (const float*)d_in[23];
    const float* W2      = (const float*)d_in[24];
    const float* b2      = (const float*)d_in[25];
    const int*   src1    = (const int*)d_in[26];
    const int*   dst1    = (const int*)d_in[27];
    const int*   src2    = (const int*)d_in[28];
    const int*   dst2    = (const int*)d_in[29];
    float* out = (float*)d_out;

#define SYMF(p, s) float* p; cudaGetSymbolAddress((void**)&p, s)
#define SYMH(p, s) __half* p; cudaGetSymbolAddress((void**)&p, s)
    SYMF(p_hlink, g_h_link);  SYMF(p_hflow, g_h_flow);
    SYMF(p_hp0, g_h_path0);   SYMF(p_hp1, g_h_path1);   SYMF(p_hp2, g_h_path2);
    SYMH(p_zs1, g_zs1);       SYMH(p_zs2, g_zs2);
    SYMF(p_el1, g_el1);       SYMF(p_er1, g_er1);
    SYMF(p_el2, g_el2);       SYMF(p_er2, g_er2);
    SYMF(p_ea, g_ea);         SYMF(p_denom, g_denom);
    SYMF(p_agg, g_agg);       SYMF(p_hidden, g_hidden);
    SYMF(p_wl1, g_wl1);       SYMF(p_wr1, g_wr1);
    SYMF(p_wl2, g_wl2);       SYMF(p_wr2, g_wr2);
    SYMF(p_ce, g_ce);         SYMF(p_wcat, g_wcat);
    SYMF(p_fc1c, g_fc1c);     SYMF(p_fc2c, g_fc2c);
    SYMF(p_rw1c, g_rw1c);     SYMF(p_rw2c, g_rw2c);
#undef SYMF
#undef SYMH

    const int T = 256;

    // --- folded weights + tf32-rounded weight copies ---
    attn_reduce_all<<<cdiv(4100 * 32, T), T>>>(
        fc_src1, attn_l1, p_wl1,  fc_dst1, attn_r1, p_wr1,
        fc_src2, attn_l2, p_wl2,  fc_dst2, attn_r2, p_wr2,
        fc_e1, attn_e1, p_ce);
    build_wcat<<<cdiv(2 * HIDN * HIDN, T), T>>>(W1, p_wcat);
    cvt_weights<<<cdiv(HIDN * NH * HD, T), T>>>(fc_src1, fc_src2, res_W1, res_W2,
                                                p_fc1c, p_fc2c, p_rw1c, p_rw2c);

    // --- node projections (tf32-rounded outputs) ---
    proj_relu<8><<<cdiv(NLINK, 32), T>>>(x_link, Wp_link, bp_link, p_hlink, NLINK);
    proj_relu<16><<<cdiv(NFLOW, 32), T>>>(x_flow, Wp_flow, bp_flow, p_hflow, NFLOW);
    proj_relu<8><<<cdiv(NPATH, 32), T>>>(x_path, Wp_path, bp_path, p_hp0, NPATH);

    // --- z_src GEMMs (fp16 outputs) ---
    {
        dim3 g1(1024 / 128, cdiv(NLINK, 128));
        mm_tf32<1, false><<<g1, T>>>(p_hlink, nullptr, p_fc1c, p_zs1,
                                     NLINK, 1024, 256, nullptr, nullptr);
        dim3 g2(1024 / 128, cdiv(NFLOW, 128));
        mm_tf32<1, false><<<g2, T>>>(p_hflow, nullptr, p_fc2c, p_zs2,
                                     NFLOW, 1024, 256, nullptr, nullptr);
    }

    // --- attn scores ---
    attn_score<<<cdiv(NLINK * 32, T), T>>>(p_hlink, p_wl1, p_el1, NLINK);
    attn_score<<<cdiv(NPATH * 32, T), T>>>(p_hp0, p_wr1, p_er1, NPATH);
    attn_score<<<cdiv(NFLOW * 32, T), T>>>(p_hflow, p_wl2, p_el2, NFLOW);

    // ================= conv 1: link -> path =================
    fill_conv_state<<<cdiv(NPATH * HIDN, T), T>>>(p_denom, p_agg);
    edge_softmax<true><<<cdiv(E1N, T), T>>>(p_el1, p_er1, e2p, p_ce, src1, dst1,
                                            p_ea, p_denom, E1N);
    edge_scatter<<<E1N, 64>>>(p_zs1, p_ea, p_denom, src1, dst1, p_agg, E1N);
    {
        dim3 g(HIDN / 128, cdiv(NPATH, 128));
        mm_tf32<2, false><<<g, T>>>(p_hp0, nullptr, p_rw1c, p_hp1,
                                    NPATH, HIDN, 256, p_agg, nullptr);
    }

    // ================= conv 2: flow -> path =================
    attn_score<<<cdiv(NPATH * 32, T), T>>>(p_hp1, p_wr2, p_er2, NPATH);
    fill_conv_state<<<cdiv(NPATH * HIDN, T), T>>>(p_denom, p_agg);
    edge_softmax<false><<<cdiv(E2N, T), T>>>(p_el2, p_er2, nullptr, nullptr, src2, dst2,
                                             p_ea, p_denom, E2N);
    edge_scatter<<<E2N, 64>>>(p_zs2, p_ea, p_denom, src2, dst2, p_agg, E2N);
    {
        dim3 g(HIDN / 128, cdiv(NPATH, 128));
        mm_tf32<2, false><<<g, T>>>(p_hp1, nullptr, p_rw2c, p_hp2,
                                    NPATH, HIDN, 256, p_agg, nullptr);
    }

    // ================= decoder (concat fused via SPLITA) =================
    {
        dim3 g(HIDN / 128, cdiv(NPATH, 128));
        mm_tf32<3, true><<<g, T>>>(p_hp2, p_hp1, p_wcat, p_hidden,
                                   NPATH, HIDN, 512, nullptr, b1);
    }
    decoder_out<<<cdiv(NPATH * 32, T), T>>>(p_hidden, W2, b2, out);
}

// round 7
// speedup vs baseline: 3.4503x; 1.2654x over previous
#include <cuda_runtime.h>
#include <cuda_fp16.h>
#include <cmath>
#include <cstdint>

#define NLINK 2000
#define NFLOW 30000
#define NPATH 50000
#define E1N   120000
#define E2N   120000
#define HIDN  256
#define NH    4
#define HD    256

// ---------------- scratch ----------------
__device__ __half g_h_link[NLINK * HIDN];
__device__ __half g_h_flow[NFLOW * HIDN];
__device__ __half g_h_path0[NPATH * HIDN];
__device__ __half g_h_path1[NPATH * HIDN];
__device__ __half g_h_path2[NPATH * HIDN];
__device__ __half g_zs1[NLINK * NH * HD];
__device__ __half g_zs2[NFLOW * NH * HD];
__device__ __half g_hidden[NPATH * HIDN];
__device__ float  g_el1[NLINK * NH];
__device__ float  g_er1[NPATH * NH];
__device__ float  g_el2[NFLOW * NH];
__device__ float  g_er2[NPATH * NH];
__device__ float  g_ea[E1N * NH];
__device__ float  g_denom[NPATH * NH];
__device__ float  g_agg[NPATH * HIDN];
__device__ float  g_wl1[HIDN * NH];
__device__ float  g_wr1[HIDN * NH];
__device__ float  g_wl2[HIDN * NH];
__device__ float  g_wr2[HIDN * NH];
__device__ float  g_ce[NH];
// fp16 transposed weights [N][K]
__device__ __half g_fc1t[NH * HD * HIDN];      // [1024][256]
__device__ __half g_fc2t[NH * HD * HIDN];      // [1024][256]
__device__ __half g_rw1t[HIDN * HIDN];         // [256][256]
__device__ __half g_rw2t[HIDN * HIDN];         // [256][256]
__device__ __half g_wcatT[HIDN * 2 * HIDN];    // [256][512]

// ---------------- helpers ----------------
__device__ __forceinline__ void mma_f16(float* c, const uint32_t* a, const uint32_t* b) {
    asm volatile(
        "mma.sync.aligned.m16n8k16.row.col.f32.f16.f16.f32 "
        "{%0,%1,%2,%3}, {%4,%5,%6,%7}, {%8,%9}, {%0,%1,%2,%3};"
        : "+f"(c[0]), "+f"(c[1]), "+f"(c[2]), "+f"(c[3])
        : "r"(a[0]), "r"(a[1]), "r"(a[2]), "r"(a[3]), "r"(b[0]), "r"(b[1]));
}

__device__ __forceinline__ void cp16(uint32_t saddr, const void* gaddr, int szbytes) {
    asm volatile("cp.async.cg.shared.global [%0], [%1], 16, %2;\n"
                 :: "r"(saddr), "l"(gaddr), "r"(szbytes));
}
__device__ __forceinline__ void cp_commit() { asm volatile("cp.async.commit_group;\n"); }
template <int W>
__device__ __forceinline__ void cp_wait() { asm volatile("cp.async.wait_group %0;\n" :: "n"(W)); }

__global__ void fill_conv_state(float* __restrict__ denom, float* __restrict__ agg) {
    int i = blockIdx.x * blockDim.x + threadIdx.x;
    if (i < NPATH * NH) denom[i] = 0.0f;
    if (i < NPATH * HIDN) agg[i] = 0.0f;
}

// transpose + fp16-convert all GEMM weights; fold W1 concat (rows 0..255 += rows 512..767)
__global__ void prep_weights(const float* __restrict__ fc1, const float* __restrict__ fc2,
                             const float* __restrict__ rw1, const float* __restrict__ rw2,
                             const float* __restrict__ W1,
                             __half* __restrict__ fc1t, __half* __restrict__ fc2t,
                             __half* __restrict__ rw1t, __half* __restrict__ rw2t,
                             __half* __restrict__ wcatT) {
    int i = blockIdx.x * blockDim.x + threadIdx.x;
    const int NFC = 1024 * 256, NRW = 256 * 256;
    if (i < NFC) {
        int n = i >> 8, k = i & 255;
        fc1t[i] = __float2half_rn(fc1[k * 1024 + n]);
        fc2t[i] = __float2half_rn(fc2[k * 1024 + n]);
    }
    if (i < NRW) {
        int n = i >> 8, k = i & 255;
        rw1t[i] = __float2half_rn(rw1[k * 256 + n]);
        rw2t[i] = __float2half_rn(rw2[k * 256 + n]);
    }
    if (i < 256 * 512) {
        int n = i >> 9, k = i & 511;
        float v = W1[k * 256 + n];
        if (k < 256) v += W1[(k + 512) * 256 + n];
        wcatT[i] = __float2half_rn(v);
    }
}

// ---------------- proj_relu: 32 rows/block, W in regs, x in smem; fp16 out ----------------
template <int KIN>
__global__ __launch_bounds__(256)
void proj_relu(const float* __restrict__ x, const float* __restrict__ W,
               const float* __restrict__ b, __half* __restrict__ out, int M) {
    __shared__ float xs[32][KIN];
    const int c = threadIdx.x;
    const int row0 = blockIdx.x * 32;
    for (int i = c; i < 32 * KIN; i += 256) {
        int r = i / KIN, k = i % KIN;
        xs[r][k] = (row0 + r < M) ? x[(size_t)(row0 + r) * KIN + k] : 0.0f;
    }
    float w[KIN];
#pragma unroll
    for (int k = 0; k < KIN; ++k) w[k] = W[k * HIDN + c];
    const float bias = b[c];
    __syncthreads();
    int rmax = min(32, M - row0);
    for (int r = 0; r < rmax; ++r) {
        float s = bias;
#pragma unroll
        for (int k = 0; k < KIN; ++k) s += xs[r][k] * w[k];
        out[(size_t)(row0 + r) * HIDN + c] = __float2half_rn(fmaxf(s, 0.0f));
    }
}

// one warp per output; 0..4095: wl1/wr1/wl2/wr2; 4096..4099: ce
__global__ void attn_reduce_all(
    const float* __restrict__ fcA, const float* __restrict__ aA, float* __restrict__ oA,
    const float* __restrict__ fcB, const float* __restrict__ aB, float* __restrict__ oB,
    const float* __restrict__ fcC, const float* __restrict__ aC, float* __restrict__ oC,
    const float* __restrict__ fcD, const float* __restrict__ aD, float* __restrict__ oD,
    const float* __restrict__ fcE, const float* __restrict__ aE, float* __restrict__ oE) {
    int gw = (blockIdx.x * blockDim.x + threadIdx.x) >> 5;
    int lane = threadIdx.x & 31;
    if (gw >= 4100) return;
    const float *fc, *at; float* out; int foff, aoff, oidx;
    if (gw < 4096) {
        int sel = gw >> 10, t = gw & 1023;
        int k = t >> 2, h = t & 3;
        switch (sel) {
            case 0: fc = fcA; at = aA; out = oA; break;
            case 1: fc = fcB; at = aB; out = oB; break;
            case 2: fc = fcC; at = aC; out = oC; break;
            default: fc = fcD; at = aD; out = oD; break;
        }
        foff = k * (NH * HD) + h * HD; aoff = h * HD; oidx = t;
    } else {
        int h = gw - 4096;
        fc = fcE; at = aE; out = oE;
        foff = h * HD; aoff = h * HD; oidx = h;
    }
    float s = 0.0f;
    for (int d = lane; d < HD; d += 32) s += fc[foff + d] * at[aoff + d];
#pragma unroll
    for (int o = 16; o > 0; o >>= 1) s += __shfl_down_sync(0xffffffffu, s, o);
    if (lane == 0) out[oidx] = s;
}

// ---------------- attn scores: warp per row, fp16 features ----------------
__device__ __forceinline__ void attn_dot_store(const __half* __restrict__ row,
                                               const float* __restrict__ w,
                                               float* __restrict__ out, int lane) {
    float s0 = 0.f, s1 = 0.f, s2 = 0.f, s3 = 0.f;
    const __half2* r2 = (const __half2*)row;
#pragma unroll
    for (int j = 0; j < 4; ++j) {
        int i2 = lane + 32 * j;                 // half2 index 0..127
        float2 f = __half22float2(r2[i2]);
        int k = 2 * i2;
        float4 w0 = *(const float4*)(w + 4 * k);
        float4 w1 = *(const float4*)(w + 4 * k + 4);
        s0 += f.x * w0.x + f.y * w1.x;
        s1 += f.x * w0.y + f.y * w1.y;
        s2 += f.x * w0.z + f.y * w1.z;
        s3 += f.x * w0.w + f.y * w1.w;
    }
#pragma unroll
    for (int o = 16; o > 0; o >>= 1) {
        s0 += __shfl_down_sync(0xffffffffu, s0, o);
        s1 += __shfl_down_sync(0xffffffffu, s1, o);
        s2 += __shfl_down_sync(0xffffffffu, s2, o);
        s3 += __shfl_down_sync(0xffffffffu, s3, o);
    }
    if (lane == 0) *(float4*)out = make_float4(s0, s1, s2, s3);
}

// merged: el1 (link), el2 (flow), er1 (path0)
__global__ void attn_score3(const __half* __restrict__ hlink, const __half* __restrict__ hflow,
                            const __half* __restrict__ hpath,
                            const float* __restrict__ wl1, const float* __restrict__ wl2,
                            const float* __restrict__ wr1,
                            float* __restrict__ el1, float* __restrict__ el2,
                            float* __restrict__ er1) {
    int gw = (blockIdx.x * blockDim.x + threadIdx.x) >> 5;
    int lane = threadIdx.x & 31;
    if (gw >= NLINK + NFLOW + NPATH) return;
    const __half* row; const float* w; float* out;
    if (gw < NLINK)               { row = hlink + (size_t)gw * HIDN; w = wl1; out = el1 + gw * 4; }
    else if (gw < NLINK + NFLOW)  { int r = gw - NLINK; row = hflow + (size_t)r * HIDN; w = wl2; out = el2 + r * 4; }
    else                          { int r = gw - NLINK - NFLOW; row = hpath + (size_t)r * HIDN; w = wr1; out = er1 + r * 4; }
    attn_dot_store(row, w, out, lane);
}

__global__ void attn_score1(const __half* __restrict__ hfeat, const float* __restrict__ w,
                            float* __restrict__ out, int M) {
    int gw = (blockIdx.x * blockDim.x + threadIdx.x) >> 5;
    int lane = threadIdx.x & 31;
    if (gw >= M) return;
    attn_dot_store(hfeat + (size_t)gw * HIDN, w, out + gw * 4, lane);
}

// ---------------- fused edge softmax (no max-shift; logits are O(1)) ----------------
template <bool HAS_EE>
__global__ void edge_softmax(const float* __restrict__ el, const float* __restrict__ er,
                             const float* __restrict__ ef, const float* __restrict__ ce,
                             const int* __restrict__ src, const int* __restrict__ dst,
                             float* __restrict__ a_out, float* __restrict__ denom, int E) {
    int e = blockIdx.x * blockDim.x + threadIdx.x;
    if (e >= E) return;
    int s = src[e], d = dst[e];
    float4 a = *(const float4*)(el + s * 4);
    float4 b = *(const float4*)(er + d * 4);
    float v[4] = { a.x + b.x, a.y + b.y, a.z + b.z, a.w + b.w };
    if (HAS_EE) {
        float f = ef[e];
        float4 c = *(const float4*)ce;
        v[0] += f * c.x; v[1] += f * c.y; v[2] += f * c.z; v[3] += f * c.w;
    }
#pragma unroll
    for (int h = 0; h < 4; ++h) {
        float lv = v[h] > 0.0f ? v[h] : 0.2f * v[h];
        v[h] = __expf(lv);
    }
    *(float4*)(a_out + e * 4) = make_float4(v[0], v[1], v[2], v[3]);
    atomicAdd(&denom[d * 4 + 0], v[0]);
    atomicAdd(&denom[d * 4 + 1], v[1]);
    atomicAdd(&denom[d * 4 + 2], v[2]);
    atomicAdd(&denom[d * 4 + 3], v[3]);
}

// ---------------- edge scatter with fp16 z ----------------
__global__ void edge_scatter(const __half* __restrict__ zs, const float* __restrict__ a_in,
                             const float* __restrict__ denom,
                             const int* __restrict__ src, const int* __restrict__ dst,
                             float* __restrict__ agg, int E) {
    int e = blockIdx.x;
    if (e >= E) return;
    int t = threadIdx.x;  // 0..63
    int s = src[e], d = dst[e];
    float al[NH];
    float4 av = *(const float4*)(a_in + e * 4);
    float4 dv = *(const float4*)(denom + d * 4);
    al[0] = 0.25f * av.x / fmaxf(dv.x, 1e-9f);
    al[1] = 0.25f * av.y / fmaxf(dv.y, 1e-9f);
    al[2] = 0.25f * av.z / fmaxf(dv.z, 1e-9f);
    al[3] = 0.25f * av.w / fmaxf(dv.w, 1e-9f);
    const uint2* z = (const uint2*)(zs + (size_t)s * (NH * HD));
    float4 r = make_float4(0.f, 0.f, 0.f, 0.f);
#pragma unroll
    for (int h = 0; h < NH; ++h) {
        uint2 u = __ldg(&z[h * 64 + t]);
        float2 f0 = __half22float2(*(const __half2*)&u.x);
        float2 f1 = __half22float2(*(const __half2*)&u.y);
        r.x += al[h] * f0.x; r.y += al[h] * f0.y;
        r.z += al[h] * f1.x; r.w += al[h] * f1.y;
    }
    float* outp = agg + (size_t)d * HIDN + t * 4;
    asm volatile("red.global.add.v4.f32 [%0], {%1,%2,%3,%4};"
                 :: "l"(outp), "f"(r.x), "f"(r.y), "f"(r.z), "f"(r.w) : "memory");
}

__global__ void decoder_out(const __half* __restrict__ hidden, const float* __restrict__ W2,
                            const float* __restrict__ b2, float* __restrict__ out) {
    int gw = (blockIdx.x * blockDim.x + threadIdx.x) >> 5;
    int lane = threadIdx.x & 31;
    if (gw >= NPATH) return;
    const __half2* hrow = (const __half2*)(hidden + (size_t)gw * HIDN);
    float s0 = 0.f, s1 = 0.f;
#pragma unroll
    for (int j = 0; j < 4; ++j) {
        int i2 = lane + 32 * j;
        float2 f = __half22float2(hrow[i2]);
        int k = 2 * i2;
        float2 w0 = *(const float2*)(W2 + 2 * k);
        float2 w1 = *(const float2*)(W2 + 2 * k + 2);
        s0 += f.x * w0.x + f.y * w1.x;
        s1 += f.x * w0.y + f.y * w1.y;
    }
#pragma unroll
    for (int o = 16; o > 0; o >>= 1) {
        s0 += __shfl_down_sync(0xffffffffu, s0, o);
        s1 += __shfl_down_sync(0xffffffffu, s1, o);
    }
    if (lane == 0) *(float2*)(out + gw * 2) = make_float2(s0 + b2[0], s1 + b2[1]);
}

// ---------------- fp16 tensor-core GEMM, 3-stage cp.async pipeline ----------------
// C[M,N] = epi(A[M,K] @ Bt[N,K]^T), fp16 in, fp32 accumulate.
// Block 128x128, 8 warps (2x4) of 64x32, BK=32. Smem rows padded to 40 halves
// (20 u32) -> conflict-free fragment loads.
// EPI: 1 = fp16 out, 2 = relu(+add[M,N]) fp16 out, 3 = relu(+bias[N]) fp16 out.
// SPLITA: A col k<256 from A, else A2 (fused concat, both [M][256]).
#define MM_STAGES 3
#define MM_TILE_U32 (128 * 20)
#define MM_SMEM_BYTES (MM_STAGES * 2 * MM_TILE_U32 * 4)
template <int EPI, bool SPLITA>
__global__ __launch_bounds__(256, 2)
void mm_f16(const __half* __restrict__ A, const __half* __restrict__ A2,
            const __half* __restrict__ Bt, void* __restrict__ Cout,
            int M, int N, int K,
            const float* __restrict__ add, const float* __restrict__ bias) {
    extern __shared__ uint32_t smem[];
    uint32_t* AsB = smem;                             // [ST][128][20]
    uint32_t* BsB = smem + MM_STAGES * MM_TILE_U32;   // [ST][128][20]
    const int tid = threadIdx.x;
    const int lane = tid & 31, wid = tid >> 5;
    const int g = lane >> 2, tig = lane & 3;
    const int warp_m = (wid >> 2) * 64, warp_n = (wid & 3) * 32;
    const int row0 = blockIdx.y * 128, col0 = blockIdx.x * 128;

    float acc[4][4][4];
#pragma unroll
    for (int i = 0; i < 4; ++i)
#pragma unroll
        for (int j = 0; j < 4; ++j)
#pragma unroll
            for (int r = 0; r < 4; ++r) acc[i][j][r] = 0.0f;

    auto issue = [&](int st, int k0) {
#pragma unroll
        for (int p = 0; p < 2; ++p) {
            int q = tid + 256 * p;
            int row = q >> 2, cik = q & 3;       // row 0..127, 16B chunk 0..3
            int c = k0 + cik * 8;                // k in halves
            // A chunk
            int r = row0 + row;
            const __half* asrc = A;
            int sz = 0;
            if (r < M) {
                sz = 16;
                if (SPLITA) asrc = (c < HIDN) ? (A + (size_t)r * HIDN + c)
                                              : (A2 + (size_t)r * HIDN + (c - HIDN));
                else        asrc = A + (size_t)r * K + c;
            }
            cp16((uint32_t)__cvta_generic_to_shared(AsB + st * MM_TILE_U32 + row * 20 + cik * 4),
                 asrc, sz);
            // B chunk
            const __half* bsrc = Bt + (size_t)(col0 + row) * K + c;
            cp16((uint32_t)__cvta_generic_to_shared(BsB + st * MM_TILE_U32 + row * 20 + cik * 4),
                 bsrc, 16);
        }
        cp_commit();
    };

    const int nIter = K / 32;
    issue(0, 0);
    issue(1, 32);
    for (int it = 0; it < nIter; ++it) {
        if (it == nIter - 1) cp_wait<0>(); else cp_wait<1>();
        __syncthreads();
        if (it + 2 < nIter) issue((it + 2) % MM_STAGES, (it + 2) * 32);
        const uint32_t* As = AsB + (it % MM_STAGES) * MM_TILE_U32;
        const uint32_t* Bs = BsB + (it % MM_STAGES) * MM_TILE_U32;
#pragma unroll
        for (int ks = 0; ks < 2; ++ks) {
            const int kb = ks * 8;               // u32 offset (16 halves)
            uint32_t af[4][4], bf[4][2];
#pragma unroll
            for (int mi = 0; mi < 4; ++mi) {
                int r = warp_m + 16 * mi + g;
                af[mi][0] = As[r * 20 + kb + tig];
                af[mi][1] = As[(r + 8) * 20 + kb + tig];
                af[mi][2] = As[r * 20 + kb + tig + 4];
                af[mi][3] = As[(r + 8) * 20 + kb + tig + 4];
            }
#pragma unroll
            for (int ni = 0; ni < 4; ++ni) {
                int n = warp_n + 8 * ni + g;
                bf[ni][0] = Bs[n * 20 + kb + tig];
                bf[ni][1] = Bs[n * 20 + kb + tig + 4];
            }
#pragma unroll
            for (int mi = 0; mi < 4; ++mi)
#pragma unroll
                for (int ni = 0; ni < 4; ++ni)
                    mma_f16(acc[mi][ni], af[mi], bf[ni]);
        }
        __syncthreads();
    }

    // epilogue: thread owns (rows g, g+8) x cols (2tig, 2tig+1) per (mi, ni)
#pragma unroll
    for (int mi = 0; mi < 4; ++mi) {
#pragma unroll
        for (int ni = 0; ni < 4; ++ni) {
            int rA = row0 + warp_m + 16 * mi + g;
            int cA = col0 + warp_n + 8 * ni + 2 * tig;
#pragma unroll
            for (int half_ = 0; half_ < 2; ++half_) {
                int r = rA + half_ * 8;
                if (r >= M) continue;
                float v0 = acc[mi][ni][half_ * 2 + 0];
                float v1 = acc[mi][ni][half_ * 2 + 1];
                if (EPI == 2) {
                    v0 = fmaxf(v0 + add[(size_t)r * N + cA + 0], 0.0f);
                    v1 = fmaxf(v1 + add[(size_t)r * N + cA + 1], 0.0f);
                } else if (EPI == 3) {
                    v0 = fmaxf(v0 + bias[cA + 0], 0.0f);
                    v1 = fmaxf(v1 + bias[cA + 1], 0.0f);
                }
                __half2* C = (__half2*)Cout;
                C[((size_t)r * N + cA) >> 1] = __floats2half2_rn(v0, v1);
            }
        }
    }
}

// ---------------- host launch ----------------
static inline int cdiv(int a, int b) { return (a + b - 1) / b; }

extern "C" void kernel_launch(void* const* d_in, const int* in_sizes, int n_in,
                              void* d_out, int out_size) {
    (void)in_sizes; (void)n_in; (void)out_size;
    const float* x_link  = (const float*)d_in[0];
    const float* x_flow  = (const float*)d_in[1];
    const float* x_path  = (const float*)d_in[2];
    const float* e2p     = (const float*)d_in[3];
    const float* Wp_link = (const float*)d_in[4];
    const float* bp_link = (const float*)d_in[5];
    const float* Wp_flow = (const float*)d_in[6];
    const float* bp_flow = (const float*)d_in[7];
    const float* Wp_path = (const float*)d_in[8];
    const float* bp_path = (const float*)d_in[9];
    const float* fc_src1 = (const float*)d_in[10];
    const float* fc_dst1 = (const float*)d_in[11];
    const float* fc_e1   = (const float*)d_in[12];
    const float* attn_l1 = (const float*)d_in[13];
    const float* attn_r1 = (const float*)d_in[14];
    const float* attn_e1 = (const float*)d_in[15];
    const float* res_W1  = (const float*)d_in[16];
    const float* fc_src2 = (const float*)d_in[17];
    const float* fc_dst2 = (const float*)d_in[18];
    const float* attn_l2 = (const float*)d_in[19];
    const float* attn_r2 = (const float*)d_in[20];
    const float* res_W2  = (const float*)d_in[21];
    const float* W1      = (const float*)d_in[22];
    const float* b1      = (const float*)d_in[23];
    const float* W2      = (const float*)d_in[24];
    const float* b2      = (const float*)d_in[25];
    const int*   src1    = (const int*)d_in[26];
    const int*   dst1    = (const int*)d_in[27];
    const int*   src2    = (const int*)d_in[28];
    const int*   dst2    = (const int*)d_in[29];
    float* out = (float*)d_out;

#define SYMF(p, s) float* p; cudaGetSymbolAddress((void**)&p, s)
#define SYMH(p, s) __half* p; cudaGetSymbolAddress((void**)&p, s)
    SYMH(p_hlink, g_h_link);  SYMH(p_hflow, g_h_flow);
    SYMH(p_hp0, g_h_path0);   SYMH(p_hp1, g_h_path1);   SYMH(p_hp2, g_h_path2);
    SYMH(p_zs1, g_zs1);       SYMH(p_zs2, g_zs2);       SYMH(p_hidden, g_hidden);
    SYMF(p_el1, g_el1);       SYMF(p_er1, g_er1);
    SYMF(p_el2, g_el2);       SYMF(p_er2, g_er2);
    SYMF(p_ea, g_ea);         SYMF(p_denom, g_denom);   SYMF(p_agg, g_agg);
    SYMF(p_wl1, g_wl1);       SYMF(p_wr1, g_wr1);
    SYMF(p_wl2, g_wl2);       SYMF(p_wr2, g_wr2);       SYMF(p_ce, g_ce);
    SYMH(p_fc1t, g_fc1t);     SYMH(p_fc2t, g_fc2t);
    SYMH(p_rw1t, g_rw1t);     SYMH(p_rw2t, g_rw2t);     SYMH(p_wcatT, g_wcatT);
#undef SYMF
#undef SYMH

    const int T = 256;

    // allow >48KB dynamic smem for the GEMM (idempotent host-side calls)
    cudaFuncSetAttribute(mm_f16<1, false>, cudaFuncAttributeMaxDynamicSharedMemorySize, MM_SMEM_BYTES);
    cudaFuncSetAttribute(mm_f16<2, false>, cudaFuncAttributeMaxDynamicSharedMemorySize, MM_SMEM_BYTES);
    cudaFuncSetAttribute(mm_f16<3, true>,  cudaFuncAttributeMaxDynamicSharedMemorySize, MM_SMEM_BYTES);

    // --- weight prep ---
    attn_reduce_all<<<cdiv(4100 * 32, T), T>>>(
        fc_src1, attn_l1, p_wl1,  fc_dst1, attn_r1, p_wr1,
        fc_src2, attn_l2, p_wl2,  fc_dst2, attn_r2, p_wr2,
        fc_e1, attn_e1, p_ce);
    prep_weights<<<cdiv(1024 * 256, T), T>>>(fc_src1, fc_src2, res_W1, res_W2, W1,
                                             p_fc1t, p_fc2t, p_rw1t, p_rw2t, p_wcatT);

    // --- node projections (fp16 out) ---
    proj_relu<8><<<cdiv(NLINK, 32), T>>>(x_link, Wp_link, bp_link, p_hlink, NLINK);
    proj_relu<16><<<cdiv(NFLOW, 32), T>>>(x_flow, Wp_flow, bp_flow, p_hflow, NFLOW);
    proj_relu<8><<<cdiv(NPATH, 32), T>>>(x_path, Wp_path, bp_path, p_hp0, NPATH);

    // --- z_src GEMMs ---
    {
        dim3 g1(1024 / 128, cdiv(NLINK, 128));
        mm_f16<1, false><<<g1, T, MM_SMEM_BYTES>>>(p_hlink, nullptr, p_fc1t, p_zs1,
                                                   NLINK, 1024, 256, nullptr, nullptr);
        dim3 g2(1024 / 128, cdiv(NFLOW, 128));
        mm_f16<1, false><<<g2, T, MM_SMEM_BYTES>>>(p_hflow, nullptr, p_fc2t, p_zs2,
                                                   NFLOW, 1024, 256, nullptr, nullptr);
    }

    // --- attn scores (merged: el1, el2, er1) ---
    attn_score3<<<cdiv((NLINK + NFLOW + NPATH) * 32, T), T>>>(
        p_hlink, p_hflow, p_hp0, p_wl1, p_wl2, p_wr1, p_el1, p_el2, p_er1);

    // ================= conv 1: link -> path =================
    fill_conv_state<<<cdiv(NPATH * HIDN, T), T>>>(p_denom, p_agg);
    edge_softmax<true><<<cdiv(E1N, T), T>>>(p_el1, p_er1, e2p, p_ce, src1, dst1,
                                            p_ea, p_denom, E1N);
    edge_scatter<<<E1N, 64>>>(p_zs1, p_ea, p_denom, src1, dst1, p_agg, E1N);
    {
        dim3 g(HIDN / 128, cdiv(NPATH, 128));
        mm_f16<2, false><<<g, T, MM_SMEM_BYTES>>>(p_hp0, nullptr, p_rw1t, p_hp1,
                                                  NPATH, HIDN, 256, p_agg, nullptr);
    }

    // ================= conv 2: flow -> path =================
    attn_score1<<<cdiv(NPATH * 32, T), T>>>(p_hp1, p_wr2, p_er2, NPATH);
    fill_conv_state<<<cdiv(NPATH * HIDN, T), T>>>(p_denom, p_agg);
    edge_softmax<false><<<cdiv(E2N, T), T>>>(p_el2, p_er2, nullptr, nullptr, src2, dst2,
                                             p_ea, p_denom, E2N);
    edge_scatter<<<E2N, 64>>>(p_zs2, p_ea, p_denom, src2, dst2, p_agg, E2N);
    {
        dim3 g(HIDN / 128, cdiv(NPATH, 128));
        mm_f16<2, false><<<g, T, MM_SMEM_BYTES>>>(p_hp1, nullptr, p_rw2t, p_hp2,
                                                  NPATH, HIDN, 256, p_agg, nullptr);
    }

    // ================= decoder (concat fused via SPLITA) =================
    {
        dim3 g(HIDN / 128, cdiv(NPATH, 128));
        mm_f16<3, true><<<g, T, MM_SMEM_BYTES>>>(p_hp2, p_hp1, p_wcatT, p_hidden,
                                                 NPATH, HIDN, 512, nullptr, b1);
    }
    decoder_out<<<cdiv(NPATH * 32, T), T>>>(p_hidden, W2, b2, out);
}

// round 9
// speedup vs baseline: 3.9040x; 1.1315x over previous
#include <cuda_runtime.h>
#include <cuda_fp16.h>
#include <cmath>
#include <cstdint>

#define NLINK 2000
#define NFLOW 30000
#define NPATH 50000
#define E1N   120000
#define E2N   120000
#define HIDN  256
#define NH    4
#define HD    256

// ---------------- scratch ----------------
__device__ __half g_h_link[NLINK * HIDN];
__device__ __half g_h_flow[NFLOW * HIDN];
__device__ __half g_h_path0[NPATH * HIDN];
__device__ __half g_h_path1[NPATH * HIDN];
__device__ __half g_h_path2[NPATH * HIDN];
__device__ __half g_zs1[NLINK * NH * HD];
__device__ __half g_zs2[NFLOW * NH * HD];
__device__ __half g_hidden[NPATH * HIDN];
__device__ float  g_el1[NLINK * NH];
__device__ float  g_er1[NPATH * NH];
__device__ float  g_el2[NFLOW * NH];
__device__ float  g_er2[NPATH * NH];
__device__ float  g_ea[E1N * NH];
__device__ float  g_denom[NPATH * NH];
__device__ float  g_agg[NPATH * HIDN];
__device__ float  g_wl1[HIDN * NH];
__device__ float  g_wr1[HIDN * NH];
__device__ float  g_wl2[HIDN * NH];
__device__ float  g_wr2[HIDN * NH];
__device__ float  g_ce[NH];
// fp16 transposed weights [N][K]
__device__ __half g_fc1t[NH * HD * HIDN];
__device__ __half g_fc2t[NH * HD * HIDN];
__device__ __half g_rw1t[HIDN * HIDN];
__device__ __half g_rw2t[HIDN * HIDN];
__device__ __half g_wcatT[HIDN * 2 * HIDN];

// ---------------- helpers ----------------
__device__ __forceinline__ void mma_f16(float* c, const uint32_t* a, const uint32_t* b) {
    asm volatile(
        "mma.sync.aligned.m16n8k16.row.col.f32.f16.f16.f32 "
        "{%0,%1,%2,%3}, {%4,%5,%6,%7}, {%8,%9}, {%0,%1,%2,%3};"
        : "+f"(c[0]), "+f"(c[1]), "+f"(c[2]), "+f"(c[3])
        : "r"(a[0]), "r"(a[1]), "r"(a[2]), "r"(a[3]), "r"(b[0]), "r"(b[1]));
}

__device__ __forceinline__ void ldsm_x4(uint32_t& r0, uint32_t& r1, uint32_t& r2,
                                        uint32_t& r3, uint32_t saddr) {
    asm volatile("ldmatrix.sync.aligned.m8n8.x4.shared.b16 {%0,%1,%2,%3}, [%4];"
                 : "=r"(r0), "=r"(r1), "=r"(r2), "=r"(r3) : "r"(saddr));
}

__device__ __forceinline__ void cp16(uint32_t saddr, const void* gaddr, int szbytes) {
    asm volatile("cp.async.cg.shared.global [%0], [%1], 16, %2;\n"
                 :: "r"(saddr), "l"(gaddr), "r"(szbytes));
}
__device__ __forceinline__ void cp_commit() { asm volatile("cp.async.commit_group;\n"); }
template <int W>
__device__ __forceinline__ void cp_wait() { asm volatile("cp.async.wait_group %0;\n" :: "n"(W)); }

__global__ void fill_conv_state(float* __restrict__ denom, float* __restrict__ agg) {
    int i = blockIdx.x * blockDim.x + threadIdx.x;
    if (i < NPATH * NH) denom[i] = 0.0f;
    if (i < NPATH * HIDN) agg[i] = 0.0f;
}

// transpose + fp16-convert all GEMM weights; fold W1 concat
__global__ void prep_weights(const float* __restrict__ fc1, const float* __restrict__ fc2,
                             const float* __restrict__ rw1, const float* __restrict__ rw2,
                             const float* __restrict__ W1,
                             __half* __restrict__ fc1t, __half* __restrict__ fc2t,
                             __half* __restrict__ rw1t, __half* __restrict__ rw2t,
                             __half* __restrict__ wcatT) {
    int i = blockIdx.x * blockDim.x + threadIdx.x;
    const int NFC = 1024 * 256, NRW = 256 * 256;
    if (i < NFC) {
        int n = i >> 8, k = i & 255;
        fc1t[i] = __float2half_rn(fc1[k * 1024 + n]);
        fc2t[i] = __float2half_rn(fc2[k * 1024 + n]);
    }
    if (i < NRW) {
        int n = i >> 8, k = i & 255;
        rw1t[i] = __float2half_rn(rw1[k * 256 + n]);
        rw2t[i] = __float2half_rn(rw2[k * 256 + n]);
    }
    if (i < 256 * 512) {
        int n = i >> 9, k = i & 511;
        float v = W1[k * 256 + n];
        if (k < 256) v += W1[(k + 512) * 256 + n];
        wcatT[i] = __float2half_rn(v);
    }
}

// ---------------- proj_relu ----------------
template <int KIN>
__global__ __launch_bounds__(256)
void proj_relu(const float* __restrict__ x, const float* __restrict__ W,
               const float* __restrict__ b, __half* __restrict__ out, int M) {
    __shared__ float xs[32][KIN];
    const int c = threadIdx.x;
    const int row0 = blockIdx.x * 32;
    for (int i = c; i < 32 * KIN; i += 256) {
        int r = i / KIN, k = i % KIN;
        xs[r][k] = (row0 + r < M) ? x[(size_t)(row0 + r) * KIN + k] : 0.0f;
    }
    float w[KIN];
#pragma unroll
    for (int k = 0; k < KIN; ++k) w[k] = W[k * HIDN + c];
    const float bias = b[c];
    __syncthreads();
    int rmax = min(32, M - row0);
    for (int r = 0; r < rmax; ++r) {
        float s = bias;
#pragma unroll
        for (int k = 0; k < KIN; ++k) s += xs[r][k] * w[k];
        out[(size_t)(row0 + r) * HIDN + c] = __float2half_rn(fmaxf(s, 0.0f));
    }
}

// one warp per output; 0..4095: wl1/wr1/wl2/wr2; 4096..4099: ce
__global__ void attn_reduce_all(
    const float* __restrict__ fcA, const float* __restrict__ aA, float* __restrict__ oA,
    const float* __restrict__ fcB, const float* __restrict__ aB, float* __restrict__ oB,
    const float* __restrict__ fcC, const float* __restrict__ aC, float* __restrict__ oC,
    const float* __restrict__ fcD, const float* __restrict__ aD, float* __restrict__ oD,
    const float* __restrict__ fcE, const float* __restrict__ aE, float* __restrict__ oE) {
    int gw = (blockIdx.x * blockDim.x + threadIdx.x) >> 5;
    int lane = threadIdx.x & 31;
    if (gw >= 4100) return;
    const float *fc, *at; float* out; int foff, aoff, oidx;
    if (gw < 4096) {
        int sel = gw >> 10, t = gw & 1023;
        int k = t >> 2, h = t & 3;
        switch (sel) {
            case 0: fc = fcA; at = aA; out = oA; break;
            case 1: fc = fcB; at = aB; out = oB; break;
            case 2: fc = fcC; at = aC; out = oC; break;
            default: fc = fcD; at = aD; out = oD; break;
        }
        foff = k * (NH * HD) + h * HD; aoff = h * HD; oidx = t;
    } else {
        int h = gw - 4096;
        fc = fcE; at = aE; out = oE;
        foff = h * HD; aoff = h * HD; oidx = h;
    }
    float s = 0.0f;
    for (int d = lane; d < HD; d += 32) s += fc[foff + d] * at[aoff + d];
#pragma unroll
    for (int o = 16; o > 0; o >>= 1) s += __shfl_down_sync(0xffffffffu, s, o);
    if (lane == 0) out[oidx] = s;
}

// ---------------- attn scores ----------------
__device__ __forceinline__ void attn_dot_store(const __half* __restrict__ row,
                                               const float* __restrict__ w,
                                               float* __restrict__ out, int lane) {
    float s0 = 0.f, s1 = 0.f, s2 = 0.f, s3 = 0.f;
    const __half2* r2 = (const __half2*)row;
#pragma unroll
    for (int j = 0; j < 4; ++j) {
        int i2 = lane + 32 * j;
        float2 f = __half22float2(r2[i2]);
        int k = 2 * i2;
        float4 w0 = *(const float4*)(w + 4 * k);
        float4 w1 = *(const float4*)(w + 4 * k + 4);
        s0 += f.x * w0.x + f.y * w1.x;
        s1 += f.x * w0.y + f.y * w1.y;
        s2 += f.x * w0.z + f.y * w1.z;
        s3 += f.x * w0.w + f.y * w1.w;
    }
#pragma unroll
    for (int o = 16; o > 0; o >>= 1) {
        s0 += __shfl_down_sync(0xffffffffu, s0, o);
        s1 += __shfl_down_sync(0xffffffffu, s1, o);
        s2 += __shfl_down_sync(0xffffffffu, s2, o);
        s3 += __shfl_down_sync(0xffffffffu, s3, o);
    }
    if (lane == 0) *(float4*)out = make_float4(s0, s1, s2, s3);
}

__global__ void attn_score3(const __half* __restrict__ hlink, const __half* __restrict__ hflow,
                            const __half* __restrict__ hpath,
                            const float* __restrict__ wl1, const float* __restrict__ wl2,
                            const float* __restrict__ wr1,
                            float* __restrict__ el1, float* __restrict__ el2,
                            float* __restrict__ er1) {
    int gw = (blockIdx.x * blockDim.x + threadIdx.x) >> 5;
    int lane = threadIdx.x & 31;
    if (gw >= NLINK + NFLOW + NPATH) return;
    const __half* row; const float* w; float* out;
    if (gw < NLINK)               { row = hlink + (size_t)gw * HIDN; w = wl1; out = el1 + gw * 4; }
    else if (gw < NLINK + NFLOW)  { int r = gw - NLINK; row = hflow + (size_t)r * HIDN; w = wl2; out = el2 + r * 4; }
    else                          { int r = gw - NLINK - NFLOW; row = hpath + (size_t)r * HIDN; w = wr1; out = er1 + r * 4; }
    attn_dot_store(row, w, out, lane);
}

__global__ void attn_score1(const __half* __restrict__ hfeat, const float* __restrict__ w,
                            float* __restrict__ out, int M) {
    int gw = (blockIdx.x * blockDim.x + threadIdx.x) >> 5;
    int lane = threadIdx.x & 31;
    if (gw >= M) return;
    attn_dot_store(hfeat + (size_t)gw * HIDN, w, out + gw * 4, lane);
}

// ---------------- fused edge softmax ----------------
template <bool HAS_EE>
__global__ void edge_softmax(const float* __restrict__ el, const float* __restrict__ er,
                             const float* __restrict__ ef, const float* __restrict__ ce,
                             const int* __restrict__ src, const int* __restrict__ dst,
                             float* __restrict__ a_out, float* __restrict__ denom, int E) {
    int e = blockIdx.x * blockDim.x + threadIdx.x;
    if (e >= E) return;
    int s = src[e], d = dst[e];
    float4 a = *(const float4*)(el + s * 4);
    float4 b = *(const float4*)(er + d * 4);
    float v[4] = { a.x + b.x, a.y + b.y, a.z + b.z, a.w + b.w };
    if (HAS_EE) {
        float f = ef[e];
        float4 c = *(const float4*)ce;
        v[0] += f * c.x; v[1] += f * c.y; v[2] += f * c.z; v[3] += f * c.w;
    }
#pragma unroll
    for (int h = 0; h < 4; ++h) {
        float lv = v[h] > 0.0f ? v[h] : 0.2f * v[h];
        v[h] = __expf(lv);
    }
    *(float4*)(a_out + e * 4) = make_float4(v[0], v[1], v[2], v[3]);
    atomicAdd(&denom[d * 4 + 0], v[0]);
    atomicAdd(&denom[d * 4 + 1], v[1]);
    atomicAdd(&denom[d * 4 + 2], v[2]);
    atomicAdd(&denom[d * 4 + 3], v[3]);
}

// ---------------- edge scatter: 8 edges per 512-thread block ----------------
__global__ __launch_bounds__(512)
void edge_scatter(const __half* __restrict__ zs, const float* __restrict__ a_in,
                  const float* __restrict__ denom,
                  const int* __restrict__ src, const int* __restrict__ dst,
                  float* __restrict__ agg, int E) {
    int e = blockIdx.x * 8 + (threadIdx.x >> 6);
    if (e >= E) return;
    int t = threadIdx.x & 63;
    int s = src[e], d = dst[e];
    float al[NH];
    float4 av = *(const float4*)(a_in + e * 4);
    float4 dv = *(const float4*)(denom + d * 4);
    al[0] = 0.25f * av.x / fmaxf(dv.x, 1e-9f);
    al[1] = 0.25f * av.y / fmaxf(dv.y, 1e-9f);
    al[2] = 0.25f * av.z / fmaxf(dv.z, 1e-9f);
    al[3] = 0.25f * av.w / fmaxf(dv.w, 1e-9f);
    const uint2* z = (const uint2*)(zs + (size_t)s * (NH * HD));
    float4 r = make_float4(0.f, 0.f, 0.f, 0.f);
#pragma unroll
    for (int h = 0; h < NH; ++h) {
        uint2 u = __ldg(&z[h * 64 + t]);
        float2 f0 = __half22float2(*(const __half2*)&u.x);
        float2 f1 = __half22float2(*(const __half2*)&u.y);
        r.x += al[h] * f0.x; r.y += al[h] * f0.y;
        r.z += al[h] * f1.x; r.w += al[h] * f1.y;
    }
    float* outp = agg + (size_t)d * HIDN + t * 4;
    asm volatile("red.global.add.v4.f32 [%0], {%1,%2,%3,%4};"
                 :: "l"(outp), "f"(r.x), "f"(r.y), "f"(r.z), "f"(r.w) : "memory");
}

__global__ void decoder_out(const __half* __restrict__ hidden, const float* __restrict__ W2,
                            const float* __restrict__ b2, float* __restrict__ out) {
    int gw = (blockIdx.x * blockDim.x + threadIdx.x) >> 5;
    int lane = threadIdx.x & 31;
    if (gw >= NPATH) return;
    const __half2* hrow = (const __half2*)(hidden + (size_t)gw * HIDN);
    float s0 = 0.f, s1 = 0.f;
#pragma unroll
    for (int j = 0; j < 4; ++j) {
        int i2 = lane + 32 * j;
        float2 f = __half22float2(hrow[i2]);
        int k = 2 * i2;
        float2 w0 = *(const float2*)(W2 + 2 * k);
        float2 w1 = *(const float2*)(W2 + 2 * k + 2);
        s0 += f.x * w0.x + f.y * w1.x;
        s1 += f.x * w0.y + f.y * w1.y;
    }
#pragma unroll
    for (int o = 16; o > 0; o >>= 1) {
        s0 += __shfl_down_sync(0xffffffffu, s0, o);
        s1 += __shfl_down_sync(0xffffffffu, s1, o);
    }
    if (lane == 0) *(float2*)(out + gw * 2) = make_float2(s0 + b2[0], s1 + b2[1]);
}

// ---------------- fp16 tensor-core GEMM, 3-stage cp.async + ldmatrix ----------------
// C[M,N] = epi(A[M,K] @ Bt[N,K]^T). Block 128x128, 8 warps of 64x32, BK=32.
// Smem rows: 40 halves (80B) -> LDSM conflict-free.
#define MM_STAGES 3
#define MM_TILE_U32 (128 * 20)
#define MM_SMEM_BYTES (MM_STAGES * 2 * MM_TILE_U32 * 4)
template <int EPI, bool SPLITA>
__global__ __launch_bounds__(256, 2)
void mm_f16(const __half* __restrict__ A, const __half* __restrict__ A2,
            const __half* __restrict__ Bt, void* __restrict__ Cout,
            int M, int N, int K,
            const float* __restrict__ add, const float* __restrict__ bias) {
    extern __shared__ uint32_t smem[];
    uint32_t* AsB = smem;
    uint32_t* BsB = smem + MM_STAGES * MM_TILE_U32;
    const int tid = threadIdx.x;
    const int lane = tid & 31, wid = tid >> 5;
    const int g = lane >> 2, tig = lane & 3;
    const int warp_m = (wid >> 2) * 64, warp_n = (wid & 3) * 32;
    const int row0 = blockIdx.y * 128, col0 = blockIdx.x * 128;

    float acc[4][4][4];
#pragma unroll
    for (int i = 0; i < 4; ++i)
#pragma unroll
        for (int j = 0; j < 4; ++j)
#pragma unroll
            for (int r = 0; r < 4; ++r) acc[i][j][r] = 0.0f;

    auto issue = [&](int st, int k0) {
#pragma unroll
        for (int p = 0; p < 2; ++p) {
            int q = tid + 256 * p;
            int row = q >> 2, cik = q & 3;
            int c = k0 + cik * 8;
            int r = row0 + row;
            const __half* asrc = A;
            int sz = 0;
            if (r < M) {
                sz = 16;
                if (SPLITA) asrc = (c < HIDN) ? (A + (size_t)r * HIDN + c)
                                              : (A2 + (size_t)r * HIDN + (c - HIDN));
                else        asrc = A + (size_t)r * K + c;
            }
            cp16((uint32_t)__cvta_generic_to_shared(AsB + st * MM_TILE_U32 + row * 20 + cik * 4),
                 asrc, sz);
            const __half* bsrc = Bt + (size_t)(col0 + row) * K + c;
            cp16((uint32_t)__cvta_generic_to_shared(BsB + st * MM_TILE_U32 + row * 20 + cik * 4),
                 bsrc, 16);
        }
        cp_commit();
    };

    // ldmatrix lane-address components (bytes)
    const uint32_t a_lane_off = ((lane & 7) + 8 * ((lane >> 3) & 1)) * 80 + 16 * (lane >> 4);
    const uint32_t b_lane_off = ((lane & 7) + 8 * (lane >> 4)) * 80 + 16 * ((lane >> 3) & 1);

    const int nIter = K / 32;
    issue(0, 0);
    issue(1, 32);
    for (int it = 0; it < nIter; ++it) {
        if (it == nIter - 1) cp_wait<0>(); else cp_wait<1>();
        __syncthreads();
        if (it + 2 < nIter) issue((it + 2) % MM_STAGES, (it + 2) * 32);
        const uint32_t As_byte =
            (uint32_t)__cvta_generic_to_shared(AsB + (it % MM_STAGES) * MM_TILE_U32);
        const uint32_t Bs_byte =
            (uint32_t)__cvta_generic_to_shared(BsB + (it % MM_STAGES) * MM_TILE_U32);
#pragma unroll
        for (int ks = 0; ks < 2; ++ks) {
            uint32_t af[4][4], bf[4][2];
#pragma unroll
            for (int mi = 0; mi < 4; ++mi)
                ldsm_x4(af[mi][0], af[mi][1], af[mi][2], af[mi][3],
                        As_byte + (warp_m + 16 * mi) * 80 + ks * 32 + a_lane_off);
#pragma unroll
            for (int np = 0; np < 2; ++np)
                ldsm_x4(bf[2 * np][0], bf[2 * np][1], bf[2 * np + 1][0], bf[2 * np + 1][1],
                        Bs_byte + (warp_n + 16 * np) * 80 + ks * 32 + b_lane_off);
#pragma unroll
            for (int mi = 0; mi < 4; ++mi)
#pragma unroll
                for (int ni = 0; ni < 4; ++ni)
                    mma_f16(acc[mi][ni], af[mi], bf[ni]);
        }
    }

#pragma unroll
    for (int mi = 0; mi < 4; ++mi) {
#pragma unroll
        for (int ni = 0; ni < 4; ++ni) {
            int rA = row0 + warp_m + 16 * mi + g;
            int cA = col0 + warp_n + 8 * ni + 2 * tig;
#pragma unroll
            for (int half_ = 0; half_ < 2; ++half_) {
                int r = rA + half_ * 8;
                if (r >= M) continue;
                float v0 = acc[mi][ni][half_ * 2 + 0];
                float v1 = acc[mi][ni][half_ * 2 + 1];
                if (EPI == 2) {
                    v0 = fmaxf(v0 + add[(size_t)r * N + cA + 0], 0.0f);
                    v1 = fmaxf(v1 + add[(size_t)r * N + cA + 1], 0.0f);
                } else if (EPI == 3) {
                    v0 = fmaxf(v0 + bias[cA + 0], 0.0f);
                    v1 = fmaxf(v1 + bias[cA + 1], 0.0f);
                }
                __half2* C = (__half2*)Cout;
                C[((size_t)r * N + cA) >> 1] = __floats2half2_rn(v0, v1);
            }
        }
    }
}

// ---------------- host launch ----------------
static inline int cdiv(int a, int b) { return (a + b - 1) / b; }

extern "C" void kernel_launch(void* const* d_in, const int* in_sizes, int n_in,
                              void* d_out, int out_size) {
    (void)in_sizes; (void)n_in; (void)out_size;
    const float* x_link  = (const float*)d_in[0];
    const float* x_flow  = (const float*)d_in[1];
    const float* x_path  = (const float*)d_in[2];
    const float* e2p     = (const float*)d_in[3];
    const float* Wp_link = (const float*)d_in[4];
    const float* bp_link = (const float*)d_in[5];
    const float* Wp_flow = (const float*)d_in[6];
    const float* bp_flow = (const float*)d_in[7];
    const float* Wp_path = (const float*)d_in[8];
    const float* bp_path = (const float*)d_in[9];
    const float* fc_src1 = (const float*)d_in[10];
    const float* fc_dst1 = (const float*)d_in[11];
    const float* fc_e1   = (const float*)d_in[12];
    const float* attn_l1 = (const float*)d_in[13];
    const float* attn_r1 = (const float*)d_in[14];
    const float* attn_e1 = (const float*)d_in[15];
    const float* res_W1  = (const float*)d_in[16];
    const float* fc_src2 = (const float*)d_in[17];
    const float* fc_dst2 = (const float*)d_in[18];
    const float* attn_l2 = (const float*)d_in[19];
    const float* attn_r2 = (const float*)d_in[20];
    const float* res_W2  = (const float*)d_in[21];
    const float* W1      = (const float*)d_in[22];
    const float* b1      = (const float*)d_in[23];
    const float* W2      = (const float*)d_in[24];
    const float* b2      = (const float*)d_in[25];
    const int*   src1    = (const int*)d_in[26];
    const int*   dst1    = (const int*)d_in[27];
    const int*   src2    = (const int*)d_in[28];
    const int*   dst2    = (const int*)d_in[29];
    float* out = (float*)d_out;

#define SYMF(p, s) float* p; cudaGetSymbolAddress((void**)&p, s)
#define SYMH(p, s) __half* p; cudaGetSymbolAddress((void**)&p, s)
    SYMH(p_hlink, g_h_link);  SYMH(p_hflow, g_h_flow);
    SYMH(p_hp0, g_h_path0);   SYMH(p_hp1, g_h_path1);   SYMH(p_hp2, g_h_path2);
    SYMH(p_zs1, g_zs1);       SYMH(p_zs2, g_zs2);       SYMH(p_hidden, g_hidden);
    SYMF(p_el1, g_el1);       SYMF(p_er1, g_er1);
    SYMF(p_el2, g_el2);       SYMF(p_er2, g_er2);
    SYMF(p_ea, g_ea);         SYMF(p_denom, g_denom);   SYMF(p_agg, g_agg);
    SYMF(p_wl1, g_wl1);       SYMF(p_wr1, g_wr1);
    SYMF(p_wl2, g_wl2);       SYMF(p_wr2, g_wr2);       SYMF(p_ce, g_ce);
    SYMH(p_fc1t, g_fc1t);     SYMH(p_fc2t, g_fc2t);
    SYMH(p_rw1t, g_rw1t);     SYMH(p_rw2t, g_rw2t);     SYMH(p_wcatT, g_wcatT);
#undef SYMF
#undef SYMH

    const int T = 256;

    cudaFuncSetAttribute(mm_f16<1, false>, cudaFuncAttributeMaxDynamicSharedMemorySize, MM_SMEM_BYTES);
    cudaFuncSetAttribute(mm_f16<2, false>, cudaFuncAttributeMaxDynamicSharedMemorySize, MM_SMEM_BYTES);
    cudaFuncSetAttribute(mm_f16<3, true>,  cudaFuncAttributeMaxDynamicSharedMemorySize, MM_SMEM_BYTES);

    // --- weight prep ---
    attn_reduce_all<<<cdiv(4100 * 32, T), T>>>(
        fc_src1, attn_l1, p_wl1,  fc_dst1, attn_r1, p_wr1,
        fc_src2, attn_l2, p_wl2,  fc_dst2, attn_r2, p_wr2,
        fc_e1, attn_e1, p_ce);
    prep_weights<<<cdiv(1024 * 256, T), T>>>(fc_src1, fc_src2, res_W1, res_W2, W1,
                                             p_fc1t, p_fc2t, p_rw1t, p_rw2t, p_wcatT);

    // --- node projections ---
    proj_relu<8><<<cdiv(NLINK, 32), T>>>(x_link, Wp_link, bp_link, p_hlink, NLINK);
    proj_relu<16><<<cdiv(NFLOW, 32), T>>>(x_flow, Wp_flow, bp_flow, p_hflow, NFLOW);
    proj_relu<8><<<cdiv(NPATH, 32), T>>>(x_path, Wp_path, bp_path, p_hp0, NPATH);

    // --- z_src GEMMs ---
    {
        dim3 g1(1024 / 128, cdiv(NLINK, 128));
        mm_f16<1, false><<<g1, T, MM_SMEM_BYTES>>>(p_hlink, nullptr, p_fc1t, p_zs1,
                                                   NLINK, 1024, 256, nullptr, nullptr);
        dim3 g2(1024 / 128, cdiv(NFLOW, 128));
        mm_f16<1, false><<<g2, T, MM_SMEM_BYTES>>>(p_hflow, nullptr, p_fc2t, p_zs2,
                                                   NFLOW, 1024, 256, nullptr, nullptr);
    }

    // --- attn scores ---
    attn_score3<<<cdiv((NLINK + NFLOW + NPATH) * 32, T), T>>>(
        p_hlink, p_hflow, p_hp0, p_wl1, p_wl2, p_wr1, p_el1, p_el2, p_er1);

    // ================= conv 1 =================
    fill_conv_state<<<cdiv(NPATH * HIDN, T), T>>>(p_denom, p_agg);
    edge_softmax<true><<<cdiv(E1N, T), T>>>(p_el1, p_er1, e2p, p_ce, src1, dst1,
                                            p_ea, p_denom, E1N);
    edge_scatter<<<cdiv(E1N, 8), 512>>>(p_zs1, p_ea, p_denom, src1, dst1, p_agg, E1N);
    {
        dim3 g(HIDN / 128, cdiv(NPATH, 128));
        mm_f16<2, false><<<g, T, MM_SMEM_BYTES>>>(p_hp0, nullptr, p_rw1t, p_hp1,
                                                  NPATH, HIDN, 256, p_agg, nullptr);
    }

    // ================= conv 2 =================
    attn_score1<<<cdiv(NPATH * 32, T), T>>>(p_hp1, p_wr2, p_er2, NPATH);
    fill_conv_state<<<cdiv(NPATH * HIDN, T), T>>>(p_denom, p_agg);
    edge_softmax<false><<<cdiv(E2N, T), T>>>(p_el2, p_er2, nullptr, nullptr, src2, dst2,
                                             p_ea, p_denom, E2N);
    edge_scatter<<<cdiv(E2N, 8), 512>>>(p_zs2, p_ea, p_denom, src2, dst2, p_agg, E2N);
    {
        dim3 g(HIDN / 128, cdiv(NPATH, 128));
        mm_f16<2, false><<<g, T, MM_SMEM_BYTES>>>(p_hp1, nullptr, p_rw2t, p_hp2,
                                                  NPATH, HIDN, 256, p_agg, nullptr);
    }

    // ================= decoder =================
    {
        dim3 g(HIDN / 128, cdiv(NPATH, 128));
        mm_f16<3, true><<<g, T, MM_SMEM_BYTES>>>(p_hp2, p_hp1, p_wcatT, p_hidden,
                                                 NPATH, HIDN, 512, nullptr, b1);
    }
    decoder_out<<<cdiv(NPATH * 32, T), T>>>(p_hidden, W2, b2, out);
}